// round 2
// baseline (speedup 1.0000x reference)
#include <cuda_runtime.h>

// Seq2Seq GRU: bi-GRU encoder (S=64) + greedy GRU decoder (31 steps).
// Strategy:
//  - vocab=128 => fold emb @ W_ih^T + b_ih into 128-row lookup tables (proj)
//  - fused recurrent GEMM: each block accumulates the 3 gate rows (j, H+j, 2H+j)
//    of W_hh and applies the GRU nonlinearity in the epilogue (no gh scratch)
//  - ping-pong h buffers (GEMM reads all of h_old while writing h_new)
//  - logits: split-K partial GEMM + deterministic reduce/argmax (greedy decode)

static const int B_  = 512;
static const int S_  = 64;
static const int T_  = 32;
static const int E_  = 512;
static const int H1  = 1024;   // encoder hidden
static const int H2  = 2048;   // decoder hidden
static const int V_  = 128;    // vocab (in & out)

// ---------------- device scratch (no allocations allowed) ----------------
__device__ float g_proj_f[V_ * 3 * H1];   // enc_emb @ W_ih_f^T + b_ih_f
__device__ float g_proj_b[V_ * 3 * H1];
__device__ float g_proj_d[V_ * 3 * H2];   // dec_emb @ W_ih_d^T + b_ih_d
__device__ float g_hf[2][B_ * H1];
__device__ float g_hb[2][B_ * H1];
__device__ float g_hh[2][B_ * H2];
__device__ float g_part[8][B_ * V_];      // split-K logits partials
__device__ int   g_tok[B_];

__device__ __forceinline__ float sigmoid_(float x) {
    return 1.f / (1.f + __expf(-x));
}
__device__ __forceinline__ float tanh_(float x) {
    // overflow-safe, accurate (~1e-6): 1 - 2/(e^{2x}+1)
    float e = __expf(2.f * x);
    return 1.f - 2.f / (e + 1.f);
}

// ---------------- projection tables: out[128][N] = Emb[128][E] @ W[N][E]^T + b ----------------
__global__ __launch_bounds__(256)
void proj_kernel(const float* __restrict__ Emb, const float* __restrict__ W,
                 const float* __restrict__ b, int which, int N)
{
    float* out = (which == 0) ? g_proj_f : (which == 1) ? g_proj_b : g_proj_d;
    const int n0 = blockIdx.x * 64, m0 = blockIdx.y * 64;
    const int tid = threadIdx.x;
    const int tx = tid & 15, ty = tid >> 4;

    __shared__ float sA[32][64];   // [k][m]
    __shared__ float sB[32][64];   // [k][n]

    float acc[4][4];
    #pragma unroll
    for (int i = 0; i < 4; i++)
        #pragma unroll
        for (int j = 0; j < 4; j++) acc[i][j] = 0.f;

    for (int k0 = 0; k0 < E_; k0 += 32) {
        #pragma unroll
        for (int it = 0; it < 2; ++it) {
            int idx = tid + it * 256;
            int r = idx >> 3, k4 = (idx & 7) * 4;
            float4 v = *(const float4*)&Emb[(m0 + r) * E_ + k0 + k4];
            sA[k4 + 0][r] = v.x; sA[k4 + 1][r] = v.y;
            sA[k4 + 2][r] = v.z; sA[k4 + 3][r] = v.w;
        }
        #pragma unroll
        for (int it = 0; it < 2; ++it) {
            int idx = tid + it * 256;
            int r = idx >> 3, k4 = (idx & 7) * 4;
            float4 v = *(const float4*)&W[(n0 + r) * E_ + k0 + k4];
            sB[k4 + 0][r] = v.x; sB[k4 + 1][r] = v.y;
            sB[k4 + 2][r] = v.z; sB[k4 + 3][r] = v.w;
        }
        __syncthreads();
        #pragma unroll
        for (int kk = 0; kk < 32; ++kk) {
            float4 a4 = *(const float4*)&sA[kk][ty * 4];
            float4 b4 = *(const float4*)&sB[kk][tx * 4];
            float a[4] = {a4.x, a4.y, a4.z, a4.w};
            float w[4] = {b4.x, b4.y, b4.z, b4.w};
            #pragma unroll
            for (int i = 0; i < 4; i++)
                #pragma unroll
                for (int j = 0; j < 4; j++)
                    acc[i][j] = fmaf(a[i], w[j], acc[i][j]);
        }
        __syncthreads();
    }

    #pragma unroll
    for (int i = 0; i < 4; i++) {
        int m = m0 + ty * 4 + i;
        #pragma unroll
        for (int j = 0; j < 4; j++) {
            int n = n0 + tx * 4 + j;
            out[m * N + n] = acc[i][j] + b[n];
        }
    }
}

// ---------------- fused GRU step: gh GEMM (3 gate rows) + gate epilogue ----------------
// HH = hidden width (= K of the GEMM; W_hh is (3*HH, HH)).
// HH==H1: encoder, blockIdx.z = direction (0 fwd, 1 bwd), token from src[b*S + t]
// HH==H2: decoder, token from g_tok[b]
template<int HH>
__global__ __launch_bounds__(256)
void gru_step_kernel(const float* __restrict__ W0, const float* __restrict__ W1,
                     const float* __restrict__ bhh0, const float* __restrict__ bhh1,
                     const int* __restrict__ toks, int pp, int s)
{
    const float* W; const float* bhh; const float* proj;
    const float* hold; float* hnew;
    int t = 0;
    if (HH == H1) {
        const int dir = blockIdx.z;
        W    = dir ? W1 : W0;
        bhh  = dir ? bhh1 : bhh0;
        proj = dir ? g_proj_b : g_proj_f;
        hold = dir ? g_hb[pp] : g_hf[pp];
        hnew = dir ? g_hb[pp ^ 1] : g_hf[pp ^ 1];
        t = dir ? (S_ - 1 - s) : s;
    } else {
        W = W0; bhh = bhh0; proj = g_proj_d;
        hold = g_hh[pp]; hnew = g_hh[pp ^ 1];
    }

    const int m0 = blockIdx.y * 64;
    const int j0 = blockIdx.x * 64;
    const int tid = threadIdx.x;
    const int tx = tid & 15, ty = tid >> 4;

    __shared__ float sA[32][64];        // [k][m]  h_old tile
    __shared__ float sW[3][32][64];     // [gate][k][j]

    float acc[3][4][4];
    #pragma unroll
    for (int g = 0; g < 3; g++)
        #pragma unroll
        for (int i = 0; i < 4; i++)
            #pragma unroll
            for (int j = 0; j < 4; j++) acc[g][i][j] = 0.f;

    for (int k0 = 0; k0 < HH; k0 += 32) {
        // h_old tile: 64 rows x 32 k  (512 float4)
        #pragma unroll
        for (int it = 0; it < 2; ++it) {
            int idx = tid + it * 256;
            int r = idx >> 3, k4 = (idx & 7) * 4;
            float4 v = *(const float4*)&hold[(m0 + r) * HH + k0 + k4];
            sA[k4 + 0][r] = v.x; sA[k4 + 1][r] = v.y;
            sA[k4 + 2][r] = v.z; sA[k4 + 3][r] = v.w;
        }
        // W tiles: 3 gates x 64 rows x 32 k  (1536 float4)
        #pragma unroll
        for (int it = 0; it < 6; ++it) {
            int idx = tid + it * 256;
            int r = idx >> 3, k4 = (idx & 7) * 4;
            int g = r >> 6, j_l = r & 63;
            float4 v = *(const float4*)&W[(g * HH + j0 + j_l) * HH + k0 + k4];
            sW[g][k4 + 0][j_l] = v.x; sW[g][k4 + 1][j_l] = v.y;
            sW[g][k4 + 2][j_l] = v.z; sW[g][k4 + 3][j_l] = v.w;
        }
        __syncthreads();
        #pragma unroll
        for (int kk = 0; kk < 32; ++kk) {
            float4 a4 = *(const float4*)&sA[kk][ty * 4];
            float a[4] = {a4.x, a4.y, a4.z, a4.w};
            #pragma unroll
            for (int g = 0; g < 3; ++g) {
                float4 w4 = *(const float4*)&sW[g][kk][tx * 4];
                float w[4] = {w4.x, w4.y, w4.z, w4.w};
                #pragma unroll
                for (int i = 0; i < 4; i++)
                    #pragma unroll
                    for (int j = 0; j < 4; j++)
                        acc[g][i][j] = fmaf(a[i], w[g == 0 ? j : j], acc[g][i][j]);
            }
        }
        __syncthreads();
    }

    // GRU gate epilogue
    #pragma unroll
    for (int i = 0; i < 4; i++) {
        const int m = m0 + ty * 4 + i;
        int token;
        if (HH == H1) token = toks[m * S_ + t];
        else          token = g_tok[m];
        const float* pr = &proj[token * (3 * HH)];
        #pragma unroll
        for (int j = 0; j < 4; j++) {
            const int jj = j0 + tx * 4 + j;
            float h_r = acc[0][i][j] + bhh[jj];
            float h_z = acc[1][i][j] + bhh[HH + jj];
            float h_n = acc[2][i][j] + bhh[2 * HH + jj];
            float i_r = pr[jj];
            float i_z = pr[HH + jj];
            float i_n = pr[2 * HH + jj];
            float r = sigmoid_(i_r + h_r);
            float z = sigmoid_(i_z + h_z);
            float n = tanh_(i_n + r * h_n);
            float ho = hold[m * HH + jj];
            hnew[m * HH + jj] = (1.f - z) * n + z * ho;
        }
    }
}

// ---------------- logits: split-K partial GEMM (32b x 128v per block) ----------------
__global__ __launch_bounds__(256)
void logits_partial_kernel(const float* __restrict__ Wfc, int pp)
{
    const float* hh = g_hh[pp ^ 1];
    const int b0 = blockIdx.x * 32;
    const int ks = blockIdx.y * 256;
    const int tid = threadIdx.x;
    const int tx = tid & 31, ty = tid >> 5;

    __shared__ float sA[32][32];    // [k][b]
    __shared__ float sB[32][128];   // [k][v]

    float acc[4][4];
    #pragma unroll
    for (int i = 0; i < 4; i++)
        #pragma unroll
        for (int j = 0; j < 4; j++) acc[i][j] = 0.f;

    for (int k0 = ks; k0 < ks + 256; k0 += 32) {
        {
            int idx = tid;
            int r = idx >> 3, k4 = (idx & 7) * 4;
            float4 v = *(const float4*)&hh[(b0 + r) * H2 + k0 + k4];
            sA[k4 + 0][r] = v.x; sA[k4 + 1][r] = v.y;
            sA[k4 + 2][r] = v.z; sA[k4 + 3][r] = v.w;
        }
        #pragma unroll
        for (int it = 0; it < 4; ++it) {
            int idx = tid + it * 256;
            int r = idx >> 3, k4 = (idx & 7) * 4;
            float4 v = *(const float4*)&Wfc[r * H2 + k0 + k4];
            sB[k4 + 0][r] = v.x; sB[k4 + 1][r] = v.y;
            sB[k4 + 2][r] = v.z; sB[k4 + 3][r] = v.w;
        }
        __syncthreads();
        #pragma unroll
        for (int kk = 0; kk < 32; ++kk) {
            float4 a4 = *(const float4*)&sA[kk][ty * 4];
            float4 b4 = *(const float4*)&sB[kk][tx * 4];
            float a[4] = {a4.x, a4.y, a4.z, a4.w};
            float w[4] = {b4.x, b4.y, b4.z, b4.w};
            #pragma unroll
            for (int i = 0; i < 4; i++)
                #pragma unroll
                for (int j = 0; j < 4; j++)
                    acc[i][j] = fmaf(a[i], w[j], acc[i][j]);
        }
        __syncthreads();
    }

    #pragma unroll
    for (int i = 0; i < 4; i++)
        #pragma unroll
        for (int j = 0; j < 4; j++)
            g_part[blockIdx.y][(b0 + ty * 4 + i) * V_ + tx * 4 + j] = acc[i][j];
}

// reduce partials + bias, write logits to out[(b*31 + t)*128 + v], argmax -> g_tok
__global__ void logits_reduce_kernel(const float* __restrict__ bfc,
                                     float* __restrict__ out, int t)
{
    const int b = blockIdx.x;
    const int v = threadIdx.x;
    float s = bfc[v];
    #pragma unroll
    for (int p = 0; p < 8; p++) s += g_part[p][b * V_ + v];
    out[(b * (T_ - 1) + t) * V_ + v] = s;

    __shared__ float sv[V_];
    __shared__ int   si[V_];
    sv[v] = s; si[v] = v;
    __syncthreads();
    for (int off = 64; off > 0; off >>= 1) {
        if (v < off) {
            float o = sv[v + off]; int oi = si[v + off];
            if (o > sv[v] || (o == sv[v] && oi < si[v])) { sv[v] = o; si[v] = oi; }
        }
        __syncthreads();
    }
    if (v == 0) g_tok[b] = si[0];
}

// ---------------- init kernels ----------------
__global__ void init_enc_kernel()
{
    int i = blockIdx.x * blockDim.x + threadIdx.x;
    if (i < B_ * H1) { g_hf[0][i] = 0.f; g_hb[0][i] = 0.f; }
}

__global__ void init_dec_kernel(const int* __restrict__ tgt)
{
    int i = blockIdx.x * blockDim.x + threadIdx.x;
    if (i < B_ * H2) {
        int b = i >> 11, j = i & (H2 - 1);
        g_hh[0][i] = (j < H1) ? g_hf[0][b * H1 + j] : g_hb[0][b * H1 + (j - H1)];
    }
    if (i < B_) g_tok[i] = tgt[i * T_];   // tgt[:, 0]
}

// ---------------- launch ----------------
extern "C" void kernel_launch(void* const* d_in, const int* in_sizes, int n_in,
                              void* d_out, int out_size)
{
    const int*   src     = (const int*)d_in[0];
    const int*   tgt     = (const int*)d_in[1];
    const float* enc_emb = (const float*)d_in[2];
    const float* dec_emb = (const float*)d_in[3];
    const float* W_ih_f  = (const float*)d_in[4];
    const float* W_hh_f  = (const float*)d_in[5];
    const float* b_ih_f  = (const float*)d_in[6];
    const float* b_hh_f  = (const float*)d_in[7];
    const float* W_ih_b  = (const float*)d_in[8];
    const float* W_hh_b  = (const float*)d_in[9];
    const float* b_ih_b  = (const float*)d_in[10];
    const float* b_hh_b  = (const float*)d_in[11];
    const float* W_ih_d  = (const float*)d_in[12];
    const float* W_hh_d  = (const float*)d_in[13];
    const float* b_ih_d  = (const float*)d_in[14];
    const float* b_hh_d  = (const float*)d_in[15];
    const float* W_fc    = (const float*)d_in[16];
    const float* b_fc    = (const float*)d_in[17];
    float* out = (float*)d_out;

    // projection lookup tables (once per replay)
    proj_kernel<<<dim3(3 * H1 / 64, 2), 256>>>(enc_emb, W_ih_f, b_ih_f, 0, 3 * H1);
    proj_kernel<<<dim3(3 * H1 / 64, 2), 256>>>(enc_emb, W_ih_b, b_ih_b, 1, 3 * H1);
    proj_kernel<<<dim3(3 * H2 / 64, 2), 256>>>(dec_emb, W_ih_d, b_ih_d, 2, 3 * H2);

    init_enc_kernel<<<(B_ * H1 + 511) / 512, 512>>>();

    // encoder: fwd + bwd in one launch (gridDim.z = 2)
    for (int s = 0; s < S_; s++)
        gru_step_kernel<H1><<<dim3(H1 / 64, B_ / 64, 2), 256>>>(
            W_hh_f, W_hh_b, b_hh_f, b_hh_b, src, s & 1, s);
    // after 64 steps (even), final h is back in buffer 0

    init_dec_kernel<<<(B_ * H2 + 511) / 512, 512>>>(tgt);

    // greedy decoder
    for (int t = 0; t < T_ - 1; t++) {
        gru_step_kernel<H2><<<dim3(H2 / 64, B_ / 64, 1), 256>>>(
            W_hh_d, W_hh_d, b_hh_d, b_hh_d, (const int*)nullptr, t & 1, 0);
        logits_partial_kernel<<<dim3(B_ / 32, 8), 256>>>(W_fc, t & 1);
        logits_reduce_kernel<<<B_, V_>>>(b_fc, out, t);
    }
}

// round 5
// speedup vs baseline: 1.0227x; 1.0227x over previous
#include <cuda_runtime.h>

// Seq2Seq GRU: bi-GRU encoder (S=64) + greedy GRU decoder (31 steps).
//  - vocab=128 => fold emb @ W_ih^T + b_ih into 128-row lookup tables (proj)
//  - fused recurrent GEMM (3 gate rows per block) + GRU epilogue, no gh scratch
//  - R2: inner products use packed fma.rn.f32x2 (FFMA2) -> 2x fp32 FMA/issue
//  - ping-pong h buffers; split-K logits + deterministic reduce/argmax

static const int B_  = 512;
static const int S_  = 64;
static const int T_  = 32;
static const int E_  = 512;
static const int H1  = 1024;   // encoder hidden
static const int H2  = 2048;   // decoder hidden
static const int V_  = 128;    // vocab (in & out)

typedef unsigned long long u64t;

__device__ __forceinline__ u64t pack2b(float v) {           // {v, v}
    u64t r; asm("mov.b64 %0, {%1, %1};" : "=l"(r) : "f"(v)); return r;
}
__device__ __forceinline__ void ffma2(u64t& acc, u64t a, u64t b) {
    asm("fma.rn.f32x2 %0, %1, %2, %0;" : "+l"(acc) : "l"(a), "l"(b));
}
__device__ __forceinline__ void unpack2(u64t v, float& lo, float& hi) {
    asm("mov.b64 {%0, %1}, %2;" : "=f"(lo), "=f"(hi) : "l"(v));
}

// ---------------- device scratch (no allocations allowed) ----------------
__device__ float g_proj_f[V_ * 3 * H1];
__device__ float g_proj_b[V_ * 3 * H1];
__device__ float g_proj_d[V_ * 3 * H2];
__device__ float g_hf[2][B_ * H1];
__device__ float g_hb[2][B_ * H1];
__device__ float g_hh[2][B_ * H2];
__device__ float g_part[8][B_ * V_];
__device__ int   g_tok[B_];

__device__ __forceinline__ float sigmoid_(float x) {
    return 1.f / (1.f + __expf(-x));
}
__device__ __forceinline__ float tanh_(float x) {
    float e = __expf(2.f * x);
    return 1.f - 2.f / (e + 1.f);
}

// ---------------- projection tables: out[128][N] = Emb[128][E] @ W[N][E]^T + b ----------------
__global__ __launch_bounds__(256)
void proj_kernel(const float* __restrict__ Emb, const float* __restrict__ W,
                 const float* __restrict__ b, int which, int N)
{
    float* out = (which == 0) ? g_proj_f : (which == 1) ? g_proj_b : g_proj_d;
    const int n0 = blockIdx.x * 64, m0 = blockIdx.y * 64;
    const int tid = threadIdx.x;
    const int tx = tid & 15, ty = tid >> 4;

    __shared__ float sA[32][64];   // [k][m]
    __shared__ float sB[32][64];   // [k][n]

    u64t accp[4][2];
    #pragma unroll
    for (int i = 0; i < 4; i++) { accp[i][0] = 0ull; accp[i][1] = 0ull; }

    for (int k0 = 0; k0 < E_; k0 += 32) {
        #pragma unroll
        for (int it = 0; it < 2; ++it) {
            int idx = tid + it * 256;
            int r = idx >> 3, k4 = (idx & 7) * 4;
            float4 v = *(const float4*)&Emb[(m0 + r) * E_ + k0 + k4];
            sA[k4 + 0][r] = v.x; sA[k4 + 1][r] = v.y;
            sA[k4 + 2][r] = v.z; sA[k4 + 3][r] = v.w;
        }
        #pragma unroll
        for (int it = 0; it < 2; ++it) {
            int idx = tid + it * 256;
            int r = idx >> 3, k4 = (idx & 7) * 4;
            float4 v = *(const float4*)&W[(n0 + r) * E_ + k0 + k4];
            sB[k4 + 0][r] = v.x; sB[k4 + 1][r] = v.y;
            sB[k4 + 2][r] = v.z; sB[k4 + 3][r] = v.w;
        }
        __syncthreads();
        #pragma unroll
        for (int kk = 0; kk < 32; ++kk) {
            float4 a4 = *(const float4*)&sA[kk][ty * 4];
            ulonglong2 w2 = *(const ulonglong2*)&sB[kk][tx * 4];
            u64t ap[4] = {pack2b(a4.x), pack2b(a4.y), pack2b(a4.z), pack2b(a4.w)};
            #pragma unroll
            for (int i = 0; i < 4; i++) {
                ffma2(accp[i][0], ap[i], w2.x);
                ffma2(accp[i][1], ap[i], w2.y);
            }
        }
        __syncthreads();
    }

    #pragma unroll
    for (int i = 0; i < 4; i++) {
        int m = m0 + ty * 4 + i;
        float a0, a1, a2, a3;
        unpack2(accp[i][0], a0, a1);
        unpack2(accp[i][1], a2, a3);
        int n = n0 + tx * 4;
        out[m * N + n + 0] = a0 + b[n + 0];
        out[m * N + n + 1] = a1 + b[n + 1];
        out[m * N + n + 2] = a2 + b[n + 2];
        out[m * N + n + 3] = a3 + b[n + 3];
    }
}

// ---------------- fused GRU step: gh GEMM (3 gate rows) + gate epilogue ----------------
template<int HH>
__global__ __launch_bounds__(256)
void gru_step_kernel(const float* __restrict__ W0, const float* __restrict__ W1,
                     const float* __restrict__ bhh0, const float* __restrict__ bhh1,
                     const int* __restrict__ toks, int pp, int s)
{
    const float* W; const float* bhh; const float* proj;
    const float* hold; float* hnew;
    int t = 0;
    if (HH == H1) {
        const int dir = blockIdx.z;
        W    = dir ? W1 : W0;
        bhh  = dir ? bhh1 : bhh0;
        proj = dir ? g_proj_b : g_proj_f;
        hold = dir ? g_hb[pp] : g_hf[pp];
        hnew = dir ? g_hb[pp ^ 1] : g_hf[pp ^ 1];
        t = dir ? (S_ - 1 - s) : s;
    } else {
        W = W0; bhh = bhh0; proj = g_proj_d;
        hold = g_hh[pp]; hnew = g_hh[pp ^ 1];
    }

    const int m0 = blockIdx.y * 64;
    const int j0 = blockIdx.x * 64;
    const int tid = threadIdx.x;
    const int tx = tid & 15, ty = tid >> 4;

    __shared__ float sA[32][64];        // [k][m]  h_old tile
    __shared__ float sW[3][32][64];     // [gate][k][j]

    u64t accp[3][4][2];                 // [gate][i][j-pair]
    #pragma unroll
    for (int g = 0; g < 3; g++)
        #pragma unroll
        for (int i = 0; i < 4; i++) { accp[g][i][0] = 0ull; accp[g][i][1] = 0ull; }

    for (int k0 = 0; k0 < HH; k0 += 32) {
        #pragma unroll
        for (int it = 0; it < 2; ++it) {
            int idx = tid + it * 256;
            int r = idx >> 3, k4 = (idx & 7) * 4;
            float4 v = *(const float4*)&hold[(m0 + r) * HH + k0 + k4];
            sA[k4 + 0][r] = v.x; sA[k4 + 1][r] = v.y;
            sA[k4 + 2][r] = v.z; sA[k4 + 3][r] = v.w;
        }
        #pragma unroll
        for (int it = 0; it < 6; ++it) {
            int idx = tid + it * 256;
            int r = idx >> 3, k4 = (idx & 7) * 4;
            int g = r >> 6, j_l = r & 63;
            float4 v = *(const float4*)&W[(g * HH + j0 + j_l) * HH + k0 + k4];
            sW[g][k4 + 0][j_l] = v.x; sW[g][k4 + 1][j_l] = v.y;
            sW[g][k4 + 2][j_l] = v.z; sW[g][k4 + 3][j_l] = v.w;
        }
        __syncthreads();
        #pragma unroll
        for (int kk = 0; kk < 32; ++kk) {
            float4 a4 = *(const float4*)&sA[kk][ty * 4];
            u64t ap[4] = {pack2b(a4.x), pack2b(a4.y), pack2b(a4.z), pack2b(a4.w)};
            #pragma unroll
            for (int g = 0; g < 3; ++g) {
                ulonglong2 w2 = *(const ulonglong2*)&sW[g][kk][tx * 4];
                #pragma unroll
                for (int i = 0; i < 4; i++) {
                    ffma2(accp[g][i][0], ap[i], w2.x);
                    ffma2(accp[g][i][1], ap[i], w2.y);
                }
            }
        }
        __syncthreads();
    }

    // GRU gate epilogue
    #pragma unroll
    for (int i = 0; i < 4; i++) {
        const int m = m0 + ty * 4 + i;
        int token;
        if (HH == H1) token = toks[m * S_ + t];
        else          token = g_tok[m];
        const float* pr = &proj[token * (3 * HH)];

        float hr[4], hz[4], hn[4];
        unpack2(accp[0][i][0], hr[0], hr[1]); unpack2(accp[0][i][1], hr[2], hr[3]);
        unpack2(accp[1][i][0], hz[0], hz[1]); unpack2(accp[1][i][1], hz[2], hz[3]);
        unpack2(accp[2][i][0], hn[0], hn[1]); unpack2(accp[2][i][1], hn[2], hn[3]);

        #pragma unroll
        for (int j = 0; j < 4; j++) {
            const int jj = j0 + tx * 4 + j;
            float h_r = hr[j] + bhh[jj];
            float h_z = hz[j] + bhh[HH + jj];
            float h_n = hn[j] + bhh[2 * HH + jj];
            float i_r = pr[jj];
            float i_z = pr[HH + jj];
            float i_n = pr[2 * HH + jj];
            float r = sigmoid_(i_r + h_r);
            float z = sigmoid_(i_z + h_z);
            float n = tanh_(i_n + r * h_n);
            float ho = hold[m * HH + jj];
            hnew[m * HH + jj] = (1.f - z) * n + z * ho;
        }
    }
}

// ---------------- logits: split-K partial GEMM (32b x 128v per block) ----------------
__global__ __launch_bounds__(256)
void logits_partial_kernel(const float* __restrict__ Wfc, int pp)
{
    const float* hh = g_hh[pp ^ 1];
    const int b0 = blockIdx.x * 32;
    const int ks = blockIdx.y * 256;
    const int tid = threadIdx.x;
    const int tx = tid & 31, ty = tid >> 5;

    __shared__ float sA[32][32];    // [k][b]
    __shared__ float sB[32][128];   // [k][v]

    u64t accp[4][2];
    #pragma unroll
    for (int i = 0; i < 4; i++) { accp[i][0] = 0ull; accp[i][1] = 0ull; }

    for (int k0 = ks; k0 < ks + 256; k0 += 32) {
        {
            int idx = tid;
            int r = idx >> 3, k4 = (idx & 7) * 4;
            float4 v = *(const float4*)&hh[(b0 + r) * H2 + k0 + k4];
            sA[k4 + 0][r] = v.x; sA[k4 + 1][r] = v.y;
            sA[k4 + 2][r] = v.z; sA[k4 + 3][r] = v.w;
        }
        #pragma unroll
        for (int it = 0; it < 4; ++it) {
            int idx = tid + it * 256;
            int r = idx >> 3, k4 = (idx & 7) * 4;
            float4 v = *(const float4*)&Wfc[r * H2 + k0 + k4];
            sB[k4 + 0][r] = v.x; sB[k4 + 1][r] = v.y;
            sB[k4 + 2][r] = v.z; sB[k4 + 3][r] = v.w;
        }
        __syncthreads();
        #pragma unroll
        for (int kk = 0; kk < 32; ++kk) {
            float4 a4 = *(const float4*)&sA[kk][ty * 4];
            ulonglong2 w2 = *(const ulonglong2*)&sB[kk][tx * 4];
            u64t ap[4] = {pack2b(a4.x), pack2b(a4.y), pack2b(a4.z), pack2b(a4.w)};
            #pragma unroll
            for (int i = 0; i < 4; i++) {
                ffma2(accp[i][0], ap[i], w2.x);
                ffma2(accp[i][1], ap[i], w2.y);
            }
        }
        __syncthreads();
    }

    #pragma unroll
    for (int i = 0; i < 4; i++) {
        float a0, a1, a2, a3;
        unpack2(accp[i][0], a0, a1);
        unpack2(accp[i][1], a2, a3);
        int row = (b0 + ty * 4 + i) * V_ + tx * 4;
        g_part[blockIdx.y][row + 0] = a0;
        g_part[blockIdx.y][row + 1] = a1;
        g_part[blockIdx.y][row + 2] = a2;
        g_part[blockIdx.y][row + 3] = a3;
    }
}

// reduce partials + bias, write logits, argmax -> g_tok
__global__ void logits_reduce_kernel(const float* __restrict__ bfc,
                                     float* __restrict__ out, int t)
{
    const int b = blockIdx.x;
    const int v = threadIdx.x;
    float s = bfc[v];
    #pragma unroll
    for (int p = 0; p < 8; p++) s += g_part[p][b * V_ + v];
    out[(b * (T_ - 1) + t) * V_ + v] = s;

    __shared__ float sv[V_];
    __shared__ int   si[V_];
    sv[v] = s; si[v] = v;
    __syncthreads();
    for (int off = 64; off > 0; off >>= 1) {
        if (v < off) {
            float o = sv[v + off]; int oi = si[v + off];
            if (o > sv[v] || (o == sv[v] && oi < si[v])) { sv[v] = o; si[v] = oi; }
        }
        __syncthreads();
    }
    if (v == 0) g_tok[b] = si[0];
}

// ---------------- init kernels ----------------
__global__ void init_enc_kernel()
{
    int i = blockIdx.x * blockDim.x + threadIdx.x;
    if (i < B_ * H1) { g_hf[0][i] = 0.f; g_hb[0][i] = 0.f; }
}

__global__ void init_dec_kernel(const int* __restrict__ tgt)
{
    int i = blockIdx.x * blockDim.x + threadIdx.x;
    if (i < B_ * H2) {
        int b = i >> 11, j = i & (H2 - 1);
        g_hh[0][i] = (j < H1) ? g_hf[0][b * H1 + j] : g_hb[0][b * H1 + (j - H1)];
    }
    if (i < B_) g_tok[i] = tgt[i * T_];   // tgt[:, 0]
}

// ---------------- launch ----------------
extern "C" void kernel_launch(void* const* d_in, const int* in_sizes, int n_in,
                              void* d_out, int out_size)
{
    const int*   src     = (const int*)d_in[0];
    const int*   tgt     = (const int*)d_in[1];
    const float* enc_emb = (const float*)d_in[2];
    const float* dec_emb = (const float*)d_in[3];
    const float* W_ih_f  = (const float*)d_in[4];
    const float* W_hh_f  = (const float*)d_in[5];
    const float* b_ih_f  = (const float*)d_in[6];
    const float* b_hh_f  = (const float*)d_in[7];
    const float* W_ih_b  = (const float*)d_in[8];
    const float* W_hh_b  = (const float*)d_in[9];
    const float* b_ih_b  = (const float*)d_in[10];
    const float* b_hh_b  = (const float*)d_in[11];
    const float* W_ih_d  = (const float*)d_in[12];
    const float* W_hh_d  = (const float*)d_in[13];
    const float* b_ih_d  = (const float*)d_in[14];
    const float* b_hh_d  = (const float*)d_in[15];
    const float* W_fc    = (const float*)d_in[16];
    const float* b_fc    = (const float*)d_in[17];
    float* out = (float*)d_out;

    proj_kernel<<<dim3(3 * H1 / 64, 2), 256>>>(enc_emb, W_ih_f, b_ih_f, 0, 3 * H1);
    proj_kernel<<<dim3(3 * H1 / 64, 2), 256>>>(enc_emb, W_ih_b, b_ih_b, 1, 3 * H1);
    proj_kernel<<<dim3(3 * H2 / 64, 2), 256>>>(dec_emb, W_ih_d, b_ih_d, 2, 3 * H2);

    init_enc_kernel<<<(B_ * H1 + 511) / 512, 512>>>();

    for (int s = 0; s < S_; s++)
        gru_step_kernel<H1><<<dim3(H1 / 64, B_ / 64, 2), 256>>>(
            W_hh_f, W_hh_b, b_hh_f, b_hh_b, src, s & 1, s);

    init_dec_kernel<<<(B_ * H2 + 511) / 512, 512>>>(tgt);

    for (int t = 0; t < T_ - 1; t++) {
        gru_step_kernel<H2><<<dim3(H2 / 64, B_ / 64, 1), 256>>>(
            W_hh_d, W_hh_d, b_hh_d, b_hh_d, (const int*)nullptr, t & 1, 0);
        logits_partial_kernel<<<dim3(B_ / 32, 8), 256>>>(W_fc, t & 1);
        logits_reduce_kernel<<<B_, V_>>>(b_fc, out, t);
    }
}

// round 6
// speedup vs baseline: 1.0231x; 1.0003x over previous
#include <cuda_runtime.h>

// Seq2Seq GRU: bi-GRU encoder (S=64) + greedy GRU decoder (31 steps).
//  - vocab=128 => fold emb @ W_ih^T + b_ih into 128-row lookup tables (proj)
//  - fused recurrent GEMM (3 gate rows per block) + GRU epilogue, no gh scratch
//  - R2: inner products use packed fma.rn.f32x2 (FFMA2) -> 2x fp32 FMA/issue
//  - ping-pong h buffers; split-K logits + deterministic reduce/argmax

static const int B_  = 512;
static const int S_  = 64;
static const int T_  = 32;
static const int E_  = 512;
static const int H1  = 1024;   // encoder hidden
static const int H2  = 2048;   // decoder hidden
static const int V_  = 128;    // vocab (in & out)

typedef unsigned long long u64t;

__device__ __forceinline__ u64t pack2b(float v) {           // {v, v}
    u64t r; asm("mov.b64 %0, {%1, %1};" : "=l"(r) : "f"(v)); return r;
}
__device__ __forceinline__ void ffma2(u64t& acc, u64t a, u64t b) {
    asm("fma.rn.f32x2 %0, %1, %2, %0;" : "+l"(acc) : "l"(a), "l"(b));
}
__device__ __forceinline__ void unpack2(u64t v, float& lo, float& hi) {
    asm("mov.b64 {%0, %1}, %2;" : "=f"(lo), "=f"(hi) : "l"(v));
}

// ---------------- device scratch (no allocations allowed) ----------------
__device__ float g_proj_f[V_ * 3 * H1];
__device__ float g_proj_b[V_ * 3 * H1];
__device__ float g_proj_d[V_ * 3 * H2];
__device__ float g_hf[2][B_ * H1];
__device__ float g_hb[2][B_ * H1];
__device__ float g_hh[2][B_ * H2];
__device__ float g_part[8][B_ * V_];
__device__ int   g_tok[B_];

__device__ __forceinline__ float sigmoid_(float x) {
    return 1.f / (1.f + __expf(-x));
}
__device__ __forceinline__ float tanh_(float x) {
    float e = __expf(2.f * x);
    return 1.f - 2.f / (e + 1.f);
}

// ---------------- projection tables: out[128][N] = Emb[128][E] @ W[N][E]^T + b ----------------
__global__ __launch_bounds__(256)
void proj_kernel(const float* __restrict__ Emb, const float* __restrict__ W,
                 const float* __restrict__ b, int which, int N)
{
    float* out = (which == 0) ? g_proj_f : (which == 1) ? g_proj_b : g_proj_d;
    const int n0 = blockIdx.x * 64, m0 = blockIdx.y * 64;
    const int tid = threadIdx.x;
    const int tx = tid & 15, ty = tid >> 4;

    __shared__ float sA[32][64];   // [k][m]
    __shared__ float sB[32][64];   // [k][n]

    u64t accp[4][2];
    #pragma unroll
    for (int i = 0; i < 4; i++) { accp[i][0] = 0ull; accp[i][1] = 0ull; }

    for (int k0 = 0; k0 < E_; k0 += 32) {
        #pragma unroll
        for (int it = 0; it < 2; ++it) {
            int idx = tid + it * 256;
            int r = idx >> 3, k4 = (idx & 7) * 4;
            float4 v = *(const float4*)&Emb[(m0 + r) * E_ + k0 + k4];
            sA[k4 + 0][r] = v.x; sA[k4 + 1][r] = v.y;
            sA[k4 + 2][r] = v.z; sA[k4 + 3][r] = v.w;
        }
        #pragma unroll
        for (int it = 0; it < 2; ++it) {
            int idx = tid + it * 256;
            int r = idx >> 3, k4 = (idx & 7) * 4;
            float4 v = *(const float4*)&W[(n0 + r) * E_ + k0 + k4];
            sB[k4 + 0][r] = v.x; sB[k4 + 1][r] = v.y;
            sB[k4 + 2][r] = v.z; sB[k4 + 3][r] = v.w;
        }
        __syncthreads();
        #pragma unroll
        for (int kk = 0; kk < 32; ++kk) {
            float4 a4 = *(const float4*)&sA[kk][ty * 4];
            ulonglong2 w2 = *(const ulonglong2*)&sB[kk][tx * 4];
            u64t ap[4] = {pack2b(a4.x), pack2b(a4.y), pack2b(a4.z), pack2b(a4.w)};
            #pragma unroll
            for (int i = 0; i < 4; i++) {
                ffma2(accp[i][0], ap[i], w2.x);
                ffma2(accp[i][1], ap[i], w2.y);
            }
        }
        __syncthreads();
    }

    #pragma unroll
    for (int i = 0; i < 4; i++) {
        int m = m0 + ty * 4 + i;
        float a0, a1, a2, a3;
        unpack2(accp[i][0], a0, a1);
        unpack2(accp[i][1], a2, a3);
        int n = n0 + tx * 4;
        out[m * N + n + 0] = a0 + b[n + 0];
        out[m * N + n + 1] = a1 + b[n + 1];
        out[m * N + n + 2] = a2 + b[n + 2];
        out[m * N + n + 3] = a3 + b[n + 3];
    }
}

// ---------------- fused GRU step: gh GEMM (3 gate rows) + gate epilogue ----------------
template<int HH>
__global__ __launch_bounds__(256)
void gru_step_kernel(const float* __restrict__ W0, const float* __restrict__ W1,
                     const float* __restrict__ bhh0, const float* __restrict__ bhh1,
                     const int* __restrict__ toks, int pp, int s)
{
    const float* W; const float* bhh; const float* proj;
    const float* hold; float* hnew;
    int t = 0;
    if (HH == H1) {
        const int dir = blockIdx.z;
        W    = dir ? W1 : W0;
        bhh  = dir ? bhh1 : bhh0;
        proj = dir ? g_proj_b : g_proj_f;
        hold = dir ? g_hb[pp] : g_hf[pp];
        hnew = dir ? g_hb[pp ^ 1] : g_hf[pp ^ 1];
        t = dir ? (S_ - 1 - s) : s;
    } else {
        W = W0; bhh = bhh0; proj = g_proj_d;
        hold = g_hh[pp]; hnew = g_hh[pp ^ 1];
    }

    const int m0 = blockIdx.y * 64;
    const int j0 = blockIdx.x * 64;
    const int tid = threadIdx.x;
    const int tx = tid & 15, ty = tid >> 4;

    __shared__ float sA[32][64];        // [k][m]  h_old tile
    __shared__ float sW[3][32][64];     // [gate][k][j]

    u64t accp[3][4][2];                 // [gate][i][j-pair]
    #pragma unroll
    for (int g = 0; g < 3; g++)
        #pragma unroll
        for (int i = 0; i < 4; i++) { accp[g][i][0] = 0ull; accp[g][i][1] = 0ull; }

    for (int k0 = 0; k0 < HH; k0 += 32) {
        #pragma unroll
        for (int it = 0; it < 2; ++it) {
            int idx = tid + it * 256;
            int r = idx >> 3, k4 = (idx & 7) * 4;
            float4 v = *(const float4*)&hold[(m0 + r) * HH + k0 + k4];
            sA[k4 + 0][r] = v.x; sA[k4 + 1][r] = v.y;
            sA[k4 + 2][r] = v.z; sA[k4 + 3][r] = v.w;
        }
        #pragma unroll
        for (int it = 0; it < 6; ++it) {
            int idx = tid + it * 256;
            int r = idx >> 3, k4 = (idx & 7) * 4;
            int g = r >> 6, j_l = r & 63;
            float4 v = *(const float4*)&W[(g * HH + j0 + j_l) * HH + k0 + k4];
            sW[g][k4 + 0][j_l] = v.x; sW[g][k4 + 1][j_l] = v.y;
            sW[g][k4 + 2][j_l] = v.z; sW[g][k4 + 3][j_l] = v.w;
        }
        __syncthreads();
        #pragma unroll
        for (int kk = 0; kk < 32; ++kk) {
            float4 a4 = *(const float4*)&sA[kk][ty * 4];
            u64t ap[4] = {pack2b(a4.x), pack2b(a4.y), pack2b(a4.z), pack2b(a4.w)};
            #pragma unroll
            for (int g = 0; g < 3; ++g) {
                ulonglong2 w2 = *(const ulonglong2*)&sW[g][kk][tx * 4];
                #pragma unroll
                for (int i = 0; i < 4; i++) {
                    ffma2(accp[g][i][0], ap[i], w2.x);
                    ffma2(accp[g][i][1], ap[i], w2.y);
                }
            }
        }
        __syncthreads();
    }

    // GRU gate epilogue
    #pragma unroll
    for (int i = 0; i < 4; i++) {
        const int m = m0 + ty * 4 + i;
        int token;
        if (HH == H1) token = toks[m * S_ + t];
        else          token = g_tok[m];
        const float* pr = &proj[token * (3 * HH)];

        float hr[4], hz[4], hn[4];
        unpack2(accp[0][i][0], hr[0], hr[1]); unpack2(accp[0][i][1], hr[2], hr[3]);
        unpack2(accp[1][i][0], hz[0], hz[1]); unpack2(accp[1][i][1], hz[2], hz[3]);
        unpack2(accp[2][i][0], hn[0], hn[1]); unpack2(accp[2][i][1], hn[2], hn[3]);

        #pragma unroll
        for (int j = 0; j < 4; j++) {
            const int jj = j0 + tx * 4 + j;
            float h_r = hr[j] + bhh[jj];
            float h_z = hz[j] + bhh[HH + jj];
            float h_n = hn[j] + bhh[2 * HH + jj];
            float i_r = pr[jj];
            float i_z = pr[HH + jj];
            float i_n = pr[2 * HH + jj];
            float r = sigmoid_(i_r + h_r);
            float z = sigmoid_(i_z + h_z);
            float n = tanh_(i_n + r * h_n);
            float ho = hold[m * HH + jj];
            hnew[m * HH + jj] = (1.f - z) * n + z * ho;
        }
    }
}

// ---------------- logits: split-K partial GEMM (32b x 128v per block) ----------------
__global__ __launch_bounds__(256)
void logits_partial_kernel(const float* __restrict__ Wfc, int pp)
{
    const float* hh = g_hh[pp ^ 1];
    const int b0 = blockIdx.x * 32;
    const int ks = blockIdx.y * 256;
    const int tid = threadIdx.x;
    const int tx = tid & 31, ty = tid >> 5;

    __shared__ float sA[32][32];    // [k][b]
    __shared__ float sB[32][128];   // [k][v]

    u64t accp[4][2];
    #pragma unroll
    for (int i = 0; i < 4; i++) { accp[i][0] = 0ull; accp[i][1] = 0ull; }

    for (int k0 = ks; k0 < ks + 256; k0 += 32) {
        {
            int idx = tid;
            int r = idx >> 3, k4 = (idx & 7) * 4;
            float4 v = *(const float4*)&hh[(b0 + r) * H2 + k0 + k4];
            sA[k4 + 0][r] = v.x; sA[k4 + 1][r] = v.y;
            sA[k4 + 2][r] = v.z; sA[k4 + 3][r] = v.w;
        }
        #pragma unroll
        for (int it = 0; it < 4; ++it) {
            int idx = tid + it * 256;
            int r = idx >> 3, k4 = (idx & 7) * 4;
            float4 v = *(const float4*)&Wfc[r * H2 + k0 + k4];
            sB[k4 + 0][r] = v.x; sB[k4 + 1][r] = v.y;
            sB[k4 + 2][r] = v.z; sB[k4 + 3][r] = v.w;
        }
        __syncthreads();
        #pragma unroll
        for (int kk = 0; kk < 32; ++kk) {
            float4 a4 = *(const float4*)&sA[kk][ty * 4];
            ulonglong2 w2 = *(const ulonglong2*)&sB[kk][tx * 4];
            u64t ap[4] = {pack2b(a4.x), pack2b(a4.y), pack2b(a4.z), pack2b(a4.w)};
            #pragma unroll
            for (int i = 0; i < 4; i++) {
                ffma2(accp[i][0], ap[i], w2.x);
                ffma2(accp[i][1], ap[i], w2.y);
            }
        }
        __syncthreads();
    }

    #pragma unroll
    for (int i = 0; i < 4; i++) {
        float a0, a1, a2, a3;
        unpack2(accp[i][0], a0, a1);
        unpack2(accp[i][1], a2, a3);
        int row = (b0 + ty * 4 + i) * V_ + tx * 4;
        g_part[blockIdx.y][row + 0] = a0;
        g_part[blockIdx.y][row + 1] = a1;
        g_part[blockIdx.y][row + 2] = a2;
        g_part[blockIdx.y][row + 3] = a3;
    }
}

// reduce partials + bias, write logits, argmax -> g_tok
__global__ void logits_reduce_kernel(const float* __restrict__ bfc,
                                     float* __restrict__ out, int t)
{
    const int b = blockIdx.x;
    const int v = threadIdx.x;
    float s = bfc[v];
    #pragma unroll
    for (int p = 0; p < 8; p++) s += g_part[p][b * V_ + v];
    out[(b * (T_ - 1) + t) * V_ + v] = s;

    __shared__ float sv[V_];
    __shared__ int   si[V_];
    sv[v] = s; si[v] = v;
    __syncthreads();
    for (int off = 64; off > 0; off >>= 1) {
        if (v < off) {
            float o = sv[v + off]; int oi = si[v + off];
            if (o > sv[v] || (o == sv[v] && oi < si[v])) { sv[v] = o; si[v] = oi; }
        }
        __syncthreads();
    }
    if (v == 0) g_tok[b] = si[0];
}

// ---------------- init kernels ----------------
__global__ void init_enc_kernel()
{
    int i = blockIdx.x * blockDim.x + threadIdx.x;
    if (i < B_ * H1) { g_hf[0][i] = 0.f; g_hb[0][i] = 0.f; }
}

__global__ void init_dec_kernel(const int* __restrict__ tgt)
{
    int i = blockIdx.x * blockDim.x + threadIdx.x;
    if (i < B_ * H2) {
        int b = i >> 11, j = i & (H2 - 1);
        g_hh[0][i] = (j < H1) ? g_hf[0][b * H1 + j] : g_hb[0][b * H1 + (j - H1)];
    }
    if (i < B_) g_tok[i] = tgt[i * T_];   // tgt[:, 0]
}

// ---------------- launch ----------------
extern "C" void kernel_launch(void* const* d_in, const int* in_sizes, int n_in,
                              void* d_out, int out_size)
{
    const int*   src     = (const int*)d_in[0];
    const int*   tgt     = (const int*)d_in[1];
    const float* enc_emb = (const float*)d_in[2];
    const float* dec_emb = (const float*)d_in[3];
    const float* W_ih_f  = (const float*)d_in[4];
    const float* W_hh_f  = (const float*)d_in[5];
    const float* b_ih_f  = (const float*)d_in[6];
    const float* b_hh_f  = (const float*)d_in[7];
    const float* W_ih_b  = (const float*)d_in[8];
    const float* W_hh_b  = (const float*)d_in[9];
    const float* b_ih_b  = (const float*)d_in[10];
    const float* b_hh_b  = (const float*)d_in[11];
    const float* W_ih_d  = (const float*)d_in[12];
    const float* W_hh_d  = (const float*)d_in[13];
    const float* b_ih_d  = (const float*)d_in[14];
    const float* b_hh_d  = (const float*)d_in[15];
    const float* W_fc    = (const float*)d_in[16];
    const float* b_fc    = (const float*)d_in[17];
    float* out = (float*)d_out;

    proj_kernel<<<dim3(3 * H1 / 64, 2), 256>>>(enc_emb, W_ih_f, b_ih_f, 0, 3 * H1);
    proj_kernel<<<dim3(3 * H1 / 64, 2), 256>>>(enc_emb, W_ih_b, b_ih_b, 1, 3 * H1);
    proj_kernel<<<dim3(3 * H2 / 64, 2), 256>>>(dec_emb, W_ih_d, b_ih_d, 2, 3 * H2);

    init_enc_kernel<<<(B_ * H1 + 511) / 512, 512>>>();

    for (int s = 0; s < S_; s++)
        gru_step_kernel<H1><<<dim3(H1 / 64, B_ / 64, 2), 256>>>(
            W_hh_f, W_hh_b, b_hh_f, b_hh_b, src, s & 1, s);

    init_dec_kernel<<<(B_ * H2 + 511) / 512, 512>>>(tgt);

    for (int t = 0; t < T_ - 1; t++) {
        gru_step_kernel<H2><<<dim3(H2 / 64, B_ / 64, 1), 256>>>(
            W_hh_d, W_hh_d, b_hh_d, b_hh_d, (const int*)nullptr, t & 1, 0);
        logits_partial_kernel<<<dim3(B_ / 32, 8), 256>>>(W_fc, t & 1);
        logits_reduce_kernel<<<B_, V_>>>(b_fc, out, t);
    }
}

// round 9
// speedup vs baseline: 2.1797x; 2.1306x over previous
#include <cuda_runtime.h>
#include <cuda_fp16.h>
#include <cstdint>

// Seq2Seq GRU with HMMA (mma.sync m16n8k16 fp16->fp32), fp32-faithful via
// 2-limb fp16 decomposition: x = h0 + h1 (22+ bits). Products h0w0+h1w0+h0w1
// realized as one fp16 GEMM over K'=3K using concatenated SMEM segments
// A=[A0|A1|A0], B=[B0|B0|B1]. Greedy decode unchanged (deterministic argmax).
//  - vocab=128 => emb @ W_ih^T + b_ih folded into lookup tables (proj)
//  - GRU step CTA: 128 batch x 32 j x 3 gates (N=96); K-chunk 64; SW128 SMEM
//  - epilogue: SMEM C roundtrip -> GRU gates -> h fp32 + fp16 limb pair

static const int B_ = 512;
static const int S_ = 64;
static const int T_ = 32;
static const int E_ = 512;
static const int H1 = 1024;
static const int H2 = 2048;
static const int V_ = 128;

// ---------------- device scratch ----------------
__device__ float g_proj_f[V_ * 3 * H1];
__device__ float g_proj_b[V_ * 3 * H1];
__device__ float g_proj_d[V_ * 3 * H2];
__device__ float g_hf[2][B_ * H1];
__device__ float g_hb[2][B_ * H1];
__device__ float g_hh[2][B_ * H2];
// fp16 limb arrays (uint4-typed for 16B-aligned vector access; 8 halfs per uint4)
__device__ uint4 g_hf_l0[2][B_ * H1 / 8];
__device__ uint4 g_hf_l1[2][B_ * H1 / 8];
__device__ uint4 g_hb_l0[2][B_ * H1 / 8];
__device__ uint4 g_hb_l1[2][B_ * H1 / 8];
__device__ uint4 g_hh_l0[2][B_ * H2 / 8];
__device__ uint4 g_hh_l1[2][B_ * H2 / 8];
__device__ uint4 g_Wf_l0[3 * H1 * H1 / 8];
__device__ uint4 g_Wf_l1[3 * H1 * H1 / 8];
__device__ uint4 g_Wb_l0[3 * H1 * H1 / 8];
__device__ uint4 g_Wb_l1[3 * H1 * H1 / 8];
__device__ uint4 g_Wd_l0[3 * H2 * H2 / 8];
__device__ uint4 g_Wd_l1[3 * H2 * H2 / 8];
__device__ float g_part[8][B_ * V_];
__device__ int   g_tok[B_];

__device__ __forceinline__ float sigmoid_(float x) { return 1.f / (1.f + __expf(-x)); }
__device__ __forceinline__ float tanh_(float x) {
    float e = __expf(2.f * x);
    return 1.f - 2.f / (e + 1.f);
}

#define SWZ(o) ((o) ^ (((o) >> 3) & 0x70))

__device__ __forceinline__ uint32_t smem_u32(const void* p) {
    uint32_t a;
    asm("{ .reg .u64 t; cvta.to.shared.u64 t, %1; cvt.u32.u64 %0, t; }" : "=r"(a) : "l"(p));
    return a;
}
__device__ __forceinline__ void split2h(float x, __half& a0, __half& a1) {
    a0 = __float2half_rn(x);
    a1 = __float2half_rn(x - __half2float(a0));
}

// ---------------- weight limb split (one-time per replay) ----------------
__global__ void split_w_kernel(const float* __restrict__ src, int which, int n)
{
    __half *o0, *o1;
    if (which == 0)      { o0 = (__half*)g_Wf_l0; o1 = (__half*)g_Wf_l1; }
    else if (which == 1) { o0 = (__half*)g_Wb_l0; o1 = (__half*)g_Wb_l1; }
    else                 { o0 = (__half*)g_Wd_l0; o1 = (__half*)g_Wd_l1; }
    int i = blockIdx.x * blockDim.x + threadIdx.x;
    if (i >= n) return;
    __half a0, a1;
    split2h(src[i], a0, a1);
    o0[i] = a0; o1[i] = a1;
}

// ---------------- projection tables: out[128][N] = Emb @ W^T + b ----------------
__global__ __launch_bounds__(256)
void proj_kernel(const float* __restrict__ Emb, const float* __restrict__ W,
                 const float* __restrict__ b, int which, int N)
{
    float* out = (which == 0) ? g_proj_f : (which == 1) ? g_proj_b : g_proj_d;
    const int n0 = blockIdx.x * 64, m0 = blockIdx.y * 64;
    const int tid = threadIdx.x;
    const int tx = tid & 15, ty = tid >> 4;

    __shared__ float sA[32][64];
    __shared__ float sB[32][64];

    float acc[4][4];
    #pragma unroll
    for (int i = 0; i < 4; i++)
        #pragma unroll
        for (int j = 0; j < 4; j++) acc[i][j] = 0.f;

    for (int k0 = 0; k0 < E_; k0 += 32) {
        #pragma unroll
        for (int it = 0; it < 2; ++it) {
            int idx = tid + it * 256;
            int r = idx >> 3, k4 = (idx & 7) * 4;
            float4 v = *(const float4*)&Emb[(m0 + r) * E_ + k0 + k4];
            sA[k4 + 0][r] = v.x; sA[k4 + 1][r] = v.y;
            sA[k4 + 2][r] = v.z; sA[k4 + 3][r] = v.w;
        }
        #pragma unroll
        for (int it = 0; it < 2; ++it) {
            int idx = tid + it * 256;
            int r = idx >> 3, k4 = (idx & 7) * 4;
            float4 v = *(const float4*)&W[(n0 + r) * E_ + k0 + k4];
            sB[k4 + 0][r] = v.x; sB[k4 + 1][r] = v.y;
            sB[k4 + 2][r] = v.z; sB[k4 + 3][r] = v.w;
        }
        __syncthreads();
        #pragma unroll
        for (int kk = 0; kk < 32; ++kk) {
            float4 a4 = *(const float4*)&sA[kk][ty * 4];
            float4 b4 = *(const float4*)&sB[kk][tx * 4];
            float a[4] = {a4.x, a4.y, a4.z, a4.w};
            float w[4] = {b4.x, b4.y, b4.z, b4.w};
            #pragma unroll
            for (int i = 0; i < 4; i++)
                #pragma unroll
                for (int j = 0; j < 4; j++)
                    acc[i][j] = fmaf(a[i], w[j], acc[i][j]);
        }
        __syncthreads();
    }

    #pragma unroll
    for (int i = 0; i < 4; i++) {
        int m = m0 + ty * 4 + i;
        #pragma unroll
        for (int j = 0; j < 4; j++) {
            int n = n0 + tx * 4 + j;
            out[m * N + n] = acc[i][j] + b[n];
        }
    }
}

// ---------------- HMMA GRU step ----------------
// CTA: 128 batch (blockIdx.y) x 32 j (blockIdx.x) x 3 gates -> N=96.
// SMEM (84KB/stage, single stage, 2 CTAs/SM overlap phases):
//   A segs s=0..2 @ s*16KB:  128x64 fp16, SW128 rows (s0=A0, s1=A1, s2=A0)
//   B segs s=0..2 @ 48KB + s*12KB: 96x64 fp16 (s0=B0, s1=B0, s2=B1)
// Epilogue reuses SMEM as fp32 C [128][100].
template<int HH>
__global__ __launch_bounds__(256, 2)
void gru_step_mma(const int* __restrict__ toks, const float* __restrict__ bhh_a,
                  const float* __restrict__ bhh_b, int pp, int s)
{
    extern __shared__ char smem[];
    const uint32_t su = smem_u32(smem);
    const int tid = threadIdx.x;

    const uint4 *w0, *w1, *h0p, *h1p;
    uint4 *hn0, *hn1;
    const float *hold, *bhh, *proj;
    float* hnew;
    int t = 0;
    if (HH == H1) {
        const int dir = blockIdx.z;
        if (dir == 0) {
            w0 = g_Wf_l0; w1 = g_Wf_l1;
            h0p = g_hf_l0[pp]; h1p = g_hf_l1[pp];
            hn0 = g_hf_l0[pp ^ 1]; hn1 = g_hf_l1[pp ^ 1];
            hold = g_hf[pp]; hnew = g_hf[pp ^ 1];
            bhh = bhh_a; proj = g_proj_f; t = s;
        } else {
            w0 = g_Wb_l0; w1 = g_Wb_l1;
            h0p = g_hb_l0[pp]; h1p = g_hb_l1[pp];
            hn0 = g_hb_l0[pp ^ 1]; hn1 = g_hb_l1[pp ^ 1];
            hold = g_hb[pp]; hnew = g_hb[pp ^ 1];
            bhh = bhh_b; proj = g_proj_b; t = S_ - 1 - s;
        }
    } else {
        w0 = g_Wd_l0; w1 = g_Wd_l1;
        h0p = g_hh_l0[pp]; h1p = g_hh_l1[pp];
        hn0 = g_hh_l0[pp ^ 1]; hn1 = g_hh_l1[pp ^ 1];
        hold = g_hh[pp]; hnew = g_hh[pp ^ 1];
        bhh = bhh_a; proj = g_proj_d;
    }

    const int m0 = blockIdx.y * 128;
    const int j0 = blockIdx.x * 32;

    const int w = tid >> 5, lane = tid & 31;
    const int wm = w >> 1, wn = w & 1;       // 4 x 2 warp grid: M=32, N=48 per warp

    float acc[2][6][4];
    #pragma unroll
    for (int mi = 0; mi < 2; ++mi)
        #pragma unroll
        for (int ni = 0; ni < 6; ++ni)
            #pragma unroll
            for (int q = 0; q < 4; ++q) acc[mi][ni][q] = 0.f;

    const int NCH = HH / 64;
    for (int c = 0; c < NCH; ++c) {
        const int k0 = c * 64;
        // stage A (h limbs): 128 rows x 8 uint4
        #pragma unroll
        for (int it = 0; it < 4; ++it) {
            int idx = tid + it * 256;
            int r = idx >> 3, kb = idx & 7;
            int gi = ((m0 + r) * HH + k0) / 8 + kb;
            uint4 v0 = h0p[gi];
            uint4 v1 = h1p[gi];
            uint32_t o = SWZ((uint32_t)(r * 128 + kb * 16));
            *(uint4*)(smem + o) = v0;
            *(uint4*)(smem + 16384 + o) = v1;
            *(uint4*)(smem + 32768 + o) = v0;
        }
        // stage B (W limbs): 96 rows (gate g = row>>5) x 8 uint4
        #pragma unroll
        for (int it = 0; it < 3; ++it) {
            int idx = tid + it * 256;
            int rsm = idx >> 3, kb = idx & 7;
            int g = rsm >> 5, jl = rsm & 31;
            int gi = ((g * HH + j0 + jl) * HH + k0) / 8 + kb;
            uint4 v0 = w0[gi];
            uint4 v1 = w1[gi];
            uint32_t o = SWZ((uint32_t)(rsm * 128 + kb * 16));
            *(uint4*)(smem + 49152 + o) = v0;
            *(uint4*)(smem + 61440 + o) = v0;
            *(uint4*)(smem + 73728 + o) = v1;
        }
        __syncthreads();

        #pragma unroll
        for (int ks = 0; ks < 12; ++ks) {
            const int sg = ks >> 2, kl = ks & 3;
            uint32_t a[2][4];
            #pragma unroll
            for (int mi = 0; mi < 2; ++mi) {
                int row = wm * 32 + mi * 16 + (lane & 15);
                uint32_t addr = su + sg * 16384
                              + SWZ((uint32_t)(row * 128 + kl * 32 + ((lane >> 4) << 4)));
                asm volatile(
                    "ldmatrix.sync.aligned.m8n8.x4.shared.b16 {%0,%1,%2,%3}, [%4];"
                    : "=r"(a[mi][0]), "=r"(a[mi][1]), "=r"(a[mi][2]), "=r"(a[mi][3])
                    : "r"(addr));
            }
            uint32_t bb[6][2];
            #pragma unroll
            for (int ni = 0; ni < 6; ++ni) {
                int n = wn * 48 + ni * 8 + (lane >> 2);
                uint32_t base = su + 49152 + sg * 12288;
                uint32_t o0 = SWZ((uint32_t)(n * 128 + kl * 32 + (lane & 3) * 4));
                uint32_t o1 = SWZ((uint32_t)(n * 128 + kl * 32 + 16 + (lane & 3) * 4));
                asm volatile("ld.shared.b32 %0, [%1];" : "=r"(bb[ni][0]) : "r"(base + o0));
                asm volatile("ld.shared.b32 %0, [%1];" : "=r"(bb[ni][1]) : "r"(base + o1));
            }
            #pragma unroll
            for (int mi = 0; mi < 2; ++mi)
                #pragma unroll
                for (int ni = 0; ni < 6; ++ni)
                    asm volatile(
                        "mma.sync.aligned.m16n8k16.row.col.f32.f16.f16.f32 "
                        "{%0,%1,%2,%3}, {%4,%5,%6,%7}, {%8,%9}, {%0,%1,%2,%3};"
                        : "+f"(acc[mi][ni][0]), "+f"(acc[mi][ni][1]),
                          "+f"(acc[mi][ni][2]), "+f"(acc[mi][ni][3])
                        : "r"(a[mi][0]), "r"(a[mi][1]), "r"(a[mi][2]), "r"(a[mi][3]),
                          "r"(bb[ni][0]), "r"(bb[ni][1]));
        }
        __syncthreads();
    }

    // ---- epilogue: C -> SMEM roundtrip (co-locate r/z/n), then gate math ----
    float* sC = (float*)smem;   // [128][100]
    #pragma unroll
    for (int mi = 0; mi < 2; ++mi)
        #pragma unroll
        for (int ni = 0; ni < 6; ++ni) {
            int row = wm * 32 + mi * 16 + (lane >> 2);
            int col = wn * 48 + ni * 8 + 2 * (lane & 3);
            sC[row * 100 + col]           = acc[mi][ni][0];
            sC[row * 100 + col + 1]       = acc[mi][ni][1];
            sC[(row + 8) * 100 + col]     = acc[mi][ni][2];
            sC[(row + 8) * 100 + col + 1] = acc[mi][ni][3];
        }
    __syncthreads();

    {
        const int m_l = tid >> 1, jh = tid & 1;
        const int mg = m0 + m_l;
        const int token = (HH == H1) ? toks[mg * S_ + t] : g_tok[mg];
        const float* pr = &proj[token * (3 * HH)];
        __half* ph0 = (__half*)hn0;
        __half* ph1 = (__half*)hn1;
        #pragma unroll
        for (int q = 0; q < 16; ++q) {
            int jl = jh * 16 + q;
            int jj = j0 + jl;
            float h_r = sC[m_l * 100 + jl]      + bhh[jj];
            float h_z = sC[m_l * 100 + 32 + jl] + bhh[HH + jj];
            float h_n = sC[m_l * 100 + 64 + jl] + bhh[2 * HH + jj];
            float r = sigmoid_(pr[jj] + h_r);
            float z = sigmoid_(pr[HH + jj] + h_z);
            float n = tanh_(pr[2 * HH + jj] + r * h_n);
            float ho = hold[mg * HH + jj];
            float hv = (1.f - z) * n + z * ho;
            hnew[mg * HH + jj] = hv;
            __half a0, a1;
            split2h(hv, a0, a1);
            ph0[mg * HH + jj] = a0;
            ph1[mg * HH + jj] = a1;
        }
    }
}

// ---------------- logits: split-K partial GEMM + reduce/argmax ----------------
__global__ __launch_bounds__(256)
void logits_partial_kernel(const float* __restrict__ Wfc, int pp)
{
    const float* hh = g_hh[pp ^ 1];
    const int b0 = blockIdx.x * 32;
    const int ks = blockIdx.y * 256;
    const int tid = threadIdx.x;
    const int tx = tid & 31, ty = tid >> 5;

    __shared__ float sA[32][32];
    __shared__ float sB[32][128];

    float acc[4][4];
    #pragma unroll
    for (int i = 0; i < 4; i++)
        #pragma unroll
        for (int j = 0; j < 4; j++) acc[i][j] = 0.f;

    for (int k0 = ks; k0 < ks + 256; k0 += 32) {
        {
            int r = tid >> 3, k4 = (tid & 7) * 4;
            float4 v = *(const float4*)&hh[(b0 + r) * H2 + k0 + k4];
            sA[k4 + 0][r] = v.x; sA[k4 + 1][r] = v.y;
            sA[k4 + 2][r] = v.z; sA[k4 + 3][r] = v.w;
        }
        #pragma unroll
        for (int it = 0; it < 4; ++it) {
            int idx = tid + it * 256;
            int r = idx >> 3, k4 = (idx & 7) * 4;
            float4 v = *(const float4*)&Wfc[r * H2 + k0 + k4];
            sB[k4 + 0][r] = v.x; sB[k4 + 1][r] = v.y;
            sB[k4 + 2][r] = v.z; sB[k4 + 3][r] = v.w;
        }
        __syncthreads();
        #pragma unroll
        for (int kk = 0; kk < 32; ++kk) {
            float4 a4 = *(const float4*)&sA[kk][ty * 4];
            float4 b4 = *(const float4*)&sB[kk][tx * 4];
            float a[4] = {a4.x, a4.y, a4.z, a4.w};
            float wv[4] = {b4.x, b4.y, b4.z, b4.w};
            #pragma unroll
            for (int i = 0; i < 4; i++)
                #pragma unroll
                for (int j = 0; j < 4; j++)
                    acc[i][j] = fmaf(a[i], wv[j], acc[i][j]);
        }
        __syncthreads();
    }

    #pragma unroll
    for (int i = 0; i < 4; i++)
        #pragma unroll
        for (int j = 0; j < 4; j++)
            g_part[blockIdx.y][(b0 + ty * 4 + i) * V_ + tx * 4 + j] = acc[i][j];
}

__global__ void logits_reduce_kernel(const float* __restrict__ bfc,
                                     float* __restrict__ out, int t)
{
    const int b = blockIdx.x;
    const int v = threadIdx.x;
    float s = bfc[v];
    #pragma unroll
    for (int p = 0; p < 8; p++) s += g_part[p][b * V_ + v];
    out[(b * (T_ - 1) + t) * V_ + v] = s;

    __shared__ float sv[V_];
    __shared__ int   si[V_];
    sv[v] = s; si[v] = v;
    __syncthreads();
    for (int off = 64; off > 0; off >>= 1) {
        if (v < off) {
            float o = sv[v + off]; int oi = si[v + off];
            if (o > sv[v] || (o == sv[v] && oi < si[v])) { sv[v] = o; si[v] = oi; }
        }
        __syncthreads();
    }
    if (v == 0) g_tok[b] = si[0];
}

// ---------------- init kernels ----------------
__global__ void init_enc_kernel()
{
    int i = blockIdx.x * blockDim.x + threadIdx.x;
    if (i < B_ * H1) { g_hf[0][i] = 0.f; g_hb[0][i] = 0.f; }
    if (i < B_ * H1 / 8) {
        uint4 z = make_uint4(0, 0, 0, 0);
        g_hf_l0[0][i] = z; g_hf_l1[0][i] = z;
        g_hb_l0[0][i] = z; g_hb_l1[0][i] = z;
    }
}

__global__ void init_dec_kernel(const int* __restrict__ tgt)
{
    int i = blockIdx.x * blockDim.x + threadIdx.x;   // one element
    if (i < B_ * H2) {
        int b = i >> 11, j = i & (H2 - 1);
        float v = (j < H1) ? g_hf[0][b * H1 + j] : g_hb[0][b * H1 + (j - H1)];
        g_hh[0][i] = v;
        __half a0, a1;
        split2h(v, a0, a1);
        ((__half*)g_hh_l0[0])[i] = a0;
        ((__half*)g_hh_l1[0])[i] = a1;
    }
    if (i < B_) g_tok[i] = tgt[i * T_];
}

// ---------------- launch ----------------
extern "C" void kernel_launch(void* const* d_in, const int* in_sizes, int n_in,
                              void* d_out, int out_size)
{
    const int*   src     = (const int*)d_in[0];
    const int*   tgt     = (const int*)d_in[1];
    const float* enc_emb = (const float*)d_in[2];
    const float* dec_emb = (const float*)d_in[3];
    const float* W_ih_f  = (const float*)d_in[4];
    const float* W_hh_f  = (const float*)d_in[5];
    const float* b_ih_f  = (const float*)d_in[6];
    const float* b_hh_f  = (const float*)d_in[7];
    const float* W_ih_b  = (const float*)d_in[8];
    const float* W_hh_b  = (const float*)d_in[9];
    const float* b_ih_b  = (const float*)d_in[10];
    const float* b_hh_b  = (const float*)d_in[11];
    const float* W_ih_d  = (const float*)d_in[12];
    const float* W_hh_d  = (const float*)d_in[13];
    const float* b_ih_d  = (const float*)d_in[14];
    const float* b_hh_d  = (const float*)d_in[15];
    const float* W_fc    = (const float*)d_in[16];
    const float* b_fc    = (const float*)d_in[17];
    float* out = (float*)d_out;

    const int SMEM = 86016;   // 84KB stage (>= 51.2KB epilogue C)
    cudaFuncSetAttribute(gru_step_mma<H1>,
        cudaFuncAttributeMaxDynamicSharedMemorySize, SMEM);
    cudaFuncSetAttribute(gru_step_mma<H2>,
        cudaFuncAttributeMaxDynamicSharedMemorySize, SMEM);

    // one-time per replay: proj tables + weight limb splits
    proj_kernel<<<dim3(3 * H1 / 64, 2), 256>>>(enc_emb, W_ih_f, b_ih_f, 0, 3 * H1);
    proj_kernel<<<dim3(3 * H1 / 64, 2), 256>>>(enc_emb, W_ih_b, b_ih_b, 1, 3 * H1);
    proj_kernel<<<dim3(3 * H2 / 64, 2), 256>>>(dec_emb, W_ih_d, b_ih_d, 2, 3 * H2);
    split_w_kernel<<<(3 * H1 * H1 + 255) / 256, 256>>>(W_hh_f, 0, 3 * H1 * H1);
    split_w_kernel<<<(3 * H1 * H1 + 255) / 256, 256>>>(W_hh_b, 1, 3 * H1 * H1);
    split_w_kernel<<<(3 * H2 * H2 + 255) / 256, 256>>>(W_hh_d, 2, 3 * H2 * H2);

    init_enc_kernel<<<(B_ * H1 + 511) / 512, 512>>>();

    for (int s = 0; s < S_; s++)
        gru_step_mma<H1><<<dim3(H1 / 32, B_ / 128, 2), 256, SMEM>>>(
            src, b_hh_f, b_hh_b, s & 1, s);
    // s=63: pp=1 -> writes buffer 0; final encoder state in buffer 0

    init_dec_kernel<<<(B_ * H2 + 255) / 256, 256>>>(tgt);

    for (int t = 0; t < T_ - 1; t++) {
        gru_step_mma<H2><<<dim3(H2 / 32, B_ / 128, 1), 256, SMEM>>>(
            (const int*)nullptr, b_hh_d, b_hh_d, t & 1, 0);
        logits_partial_kernel<<<dim3(B_ / 32, 8), 256>>>(W_fc, t & 1);
        logits_reduce_kernel<<<B_, V_>>>(b_fc, out, t);
    }
}

// round 10
// speedup vs baseline: 2.6423x; 1.2122x over previous
#include <cuda_runtime.h>
#include <cuda_fp16.h>
#include <cstdint>

// Seq2Seq GRU with HMMA (mma.sync m16n8k16 fp16->fp32), fp32-faithful via
// 2-limb fp16 decomposition x = h0 + h1 (22+ mantissa bits); 3 limb products
// (A0B0 + A1B0 + A0B1) issued from registers (limb reuse, no segment dup).
// R10: cp.async double-buffered staging (2 x 56KB), SMEM traffic -33%.
//  - vocab=128 => emb @ W_ih^T + b_ih folded into lookup tables (proj)
//  - GRU step CTA: 128 batch x 32 j x 3 gates (N=96); K-chunk 64; SW128 SMEM
//  - epilogue: SMEM C roundtrip -> GRU gates -> h fp32 + fp16 limb pair

static const int B_ = 512;
static const int S_ = 64;
static const int T_ = 32;
static const int E_ = 512;
static const int H1 = 1024;
static const int H2 = 2048;
static const int V_ = 128;

// stage layout (bytes): A0 @ 0 (16K), A1 @ 16K, B0 @ 32K (12K), B1 @ 44K; 56K total
static const int STG_BYTES = 57344;
static const int OFF_A1 = 16384;
static const int OFF_B0 = 32768;
static const int OFF_B1 = 45056;

// ---------------- device scratch ----------------
__device__ float g_proj_f[V_ * 3 * H1];
__device__ float g_proj_b[V_ * 3 * H1];
__device__ float g_proj_d[V_ * 3 * H2];
__device__ float g_hf[2][B_ * H1];
__device__ float g_hb[2][B_ * H1];
__device__ float g_hh[2][B_ * H2];
__device__ uint4 g_hf_l0[2][B_ * H1 / 8];
__device__ uint4 g_hf_l1[2][B_ * H1 / 8];
__device__ uint4 g_hb_l0[2][B_ * H1 / 8];
__device__ uint4 g_hb_l1[2][B_ * H1 / 8];
__device__ uint4 g_hh_l0[2][B_ * H2 / 8];
__device__ uint4 g_hh_l1[2][B_ * H2 / 8];
__device__ uint4 g_Wf_l0[3 * H1 * H1 / 8];
__device__ uint4 g_Wf_l1[3 * H1 * H1 / 8];
__device__ uint4 g_Wb_l0[3 * H1 * H1 / 8];
__device__ uint4 g_Wb_l1[3 * H1 * H1 / 8];
__device__ uint4 g_Wd_l0[3 * H2 * H2 / 8];
__device__ uint4 g_Wd_l1[3 * H2 * H2 / 8];
__device__ float g_part[8][B_ * V_];
__device__ int   g_tok[B_];

__device__ __forceinline__ float sigmoid_(float x) { return 1.f / (1.f + __expf(-x)); }
__device__ __forceinline__ float tanh_(float x) {
    float e = __expf(2.f * x);
    return 1.f - 2.f / (e + 1.f);
}

#define SWZ(o) ((o) ^ (((o) >> 3) & 0x70))

__device__ __forceinline__ uint32_t smem_u32(const void* p) {
    uint32_t a;
    asm("{ .reg .u64 t; cvta.to.shared.u64 t, %1; cvt.u32.u64 %0, t; }" : "=r"(a) : "l"(p));
    return a;
}
__device__ __forceinline__ void split2h(float x, __half& a0, __half& a1) {
    a0 = __float2half_rn(x);
    a1 = __float2half_rn(x - __half2float(a0));
}
__device__ __forceinline__ void cp16(uint32_t dst, const void* src) {
    asm volatile("cp.async.cg.shared.global [%0], [%1], 16;" :: "r"(dst), "l"(src));
}
__device__ __forceinline__ void cp_commit() {
    asm volatile("cp.async.commit_group;" ::: "memory");
}
template<int N>
__device__ __forceinline__ void cp_wait() {
    asm volatile("cp.async.wait_group %0;" :: "n"(N) : "memory");
}

// ---------------- weight limb split (one-time per replay) ----------------
__global__ void split_w_kernel(const float* __restrict__ src, int which, int n)
{
    __half *o0, *o1;
    if (which == 0)      { o0 = (__half*)g_Wf_l0; o1 = (__half*)g_Wf_l1; }
    else if (which == 1) { o0 = (__half*)g_Wb_l0; o1 = (__half*)g_Wb_l1; }
    else                 { o0 = (__half*)g_Wd_l0; o1 = (__half*)g_Wd_l1; }
    int i = blockIdx.x * blockDim.x + threadIdx.x;
    if (i >= n) return;
    __half a0, a1;
    split2h(src[i], a0, a1);
    o0[i] = a0; o1[i] = a1;
}

// ---------------- projection tables: out[128][N] = Emb @ W^T + b ----------------
__global__ __launch_bounds__(256)
void proj_kernel(const float* __restrict__ Emb, const float* __restrict__ W,
                 const float* __restrict__ b, int which, int N)
{
    float* out = (which == 0) ? g_proj_f : (which == 1) ? g_proj_b : g_proj_d;
    const int n0 = blockIdx.x * 64, m0 = blockIdx.y * 64;
    const int tid = threadIdx.x;
    const int tx = tid & 15, ty = tid >> 4;

    __shared__ float sA[32][64];
    __shared__ float sB[32][64];

    float acc[4][4];
    #pragma unroll
    for (int i = 0; i < 4; i++)
        #pragma unroll
        for (int j = 0; j < 4; j++) acc[i][j] = 0.f;

    for (int k0 = 0; k0 < E_; k0 += 32) {
        #pragma unroll
        for (int it = 0; it < 2; ++it) {
            int idx = tid + it * 256;
            int r = idx >> 3, k4 = (idx & 7) * 4;
            float4 v = *(const float4*)&Emb[(m0 + r) * E_ + k0 + k4];
            sA[k4 + 0][r] = v.x; sA[k4 + 1][r] = v.y;
            sA[k4 + 2][r] = v.z; sA[k4 + 3][r] = v.w;
        }
        #pragma unroll
        for (int it = 0; it < 2; ++it) {
            int idx = tid + it * 256;
            int r = idx >> 3, k4 = (idx & 7) * 4;
            float4 v = *(const float4*)&W[(n0 + r) * E_ + k0 + k4];
            sB[k4 + 0][r] = v.x; sB[k4 + 1][r] = v.y;
            sB[k4 + 2][r] = v.z; sB[k4 + 3][r] = v.w;
        }
        __syncthreads();
        #pragma unroll
        for (int kk = 0; kk < 32; ++kk) {
            float4 a4 = *(const float4*)&sA[kk][ty * 4];
            float4 b4 = *(const float4*)&sB[kk][tx * 4];
            float a[4] = {a4.x, a4.y, a4.z, a4.w};
            float w[4] = {b4.x, b4.y, b4.z, b4.w};
            #pragma unroll
            for (int i = 0; i < 4; i++)
                #pragma unroll
                for (int j = 0; j < 4; j++)
                    acc[i][j] = fmaf(a[i], w[j], acc[i][j]);
        }
        __syncthreads();
    }

    #pragma unroll
    for (int i = 0; i < 4; i++) {
        int m = m0 + ty * 4 + i;
        #pragma unroll
        for (int j = 0; j < 4; j++) {
            int n = n0 + tx * 4 + j;
            out[m * N + n] = acc[i][j] + b[n];
        }
    }
}

// ---------------- HMMA GRU step (limb reuse + cp.async pipeline) ----------------
// CTA: 128 batch (blockIdx.y) x 32 j (blockIdx.x) x 3 gates -> N=96.
// 2 stages x 56KB; epilogue reuses SMEM as fp32 C [128][100].
template<int HH>
__global__ __launch_bounds__(256, 2)
void gru_step_mma(const int* __restrict__ toks, const float* __restrict__ bhh_a,
                  const float* __restrict__ bhh_b, int pp, int s)
{
    extern __shared__ char smem[];
    const uint32_t su = smem_u32(smem);
    const int tid = threadIdx.x;

    const uint4 *w0, *w1, *h0p, *h1p;
    uint4 *hn0, *hn1;
    const float *hold, *bhh, *proj;
    float* hnew;
    int t = 0;
    if (HH == H1) {
        const int dir = blockIdx.z;
        if (dir == 0) {
            w0 = g_Wf_l0; w1 = g_Wf_l1;
            h0p = g_hf_l0[pp]; h1p = g_hf_l1[pp];
            hn0 = g_hf_l0[pp ^ 1]; hn1 = g_hf_l1[pp ^ 1];
            hold = g_hf[pp]; hnew = g_hf[pp ^ 1];
            bhh = bhh_a; proj = g_proj_f; t = s;
        } else {
            w0 = g_Wb_l0; w1 = g_Wb_l1;
            h0p = g_hb_l0[pp]; h1p = g_hb_l1[pp];
            hn0 = g_hb_l0[pp ^ 1]; hn1 = g_hb_l1[pp ^ 1];
            hold = g_hb[pp]; hnew = g_hb[pp ^ 1];
            bhh = bhh_b; proj = g_proj_b; t = S_ - 1 - s;
        }
    } else {
        w0 = g_Wd_l0; w1 = g_Wd_l1;
        h0p = g_hh_l0[pp]; h1p = g_hh_l1[pp];
        hn0 = g_hh_l0[pp ^ 1]; hn1 = g_hh_l1[pp ^ 1];
        hold = g_hh[pp]; hnew = g_hh[pp ^ 1];
        bhh = bhh_a; proj = g_proj_d;
    }

    const int m0 = blockIdx.y * 128;
    const int j0 = blockIdx.x * 32;

    const int w = tid >> 5, lane = tid & 31;
    const int wm = w >> 1, wn = w & 1;       // 4 x 2 warp grid: M=32, N=48 per warp

    float acc[2][6][4];
    #pragma unroll
    for (int mi = 0; mi < 2; ++mi)
        #pragma unroll
        for (int ni = 0; ni < 6; ++ni)
            #pragma unroll
            for (int q = 0; q < 4; ++q) acc[mi][ni][q] = 0.f;

    const int NCH = HH / 64;

    // ---- staging via cp.async (A limbs 32KB, B limbs 24KB, no duplication) ----
    auto stage_load = [&](int c, int st) {
        const int k0 = c * 64;
        const uint32_t sb = su + st * STG_BYTES;
        #pragma unroll
        for (int it = 0; it < 4; ++it) {
            int idx = tid + it * 256;
            int r = idx >> 3, kb = idx & 7;
            int gi = ((m0 + r) * HH + k0) / 8 + kb;
            uint32_t o = SWZ((uint32_t)(r * 128 + kb * 16));
            cp16(sb + o, &h0p[gi]);
            cp16(sb + OFF_A1 + o, &h1p[gi]);
        }
        #pragma unroll
        for (int it = 0; it < 3; ++it) {
            int idx = tid + it * 256;
            int rsm = idx >> 3, kb = idx & 7;
            int g = rsm >> 5, jl = rsm & 31;
            int gi = ((g * HH + j0 + jl) * HH + k0) / 8 + kb;
            uint32_t o = SWZ((uint32_t)(rsm * 128 + kb * 16));
            cp16(sb + OFF_B0 + o, &w0[gi]);
            cp16(sb + OFF_B1 + o, &w1[gi]);
        }
    };

    stage_load(0, 0);
    cp_commit();

    for (int c = 0; c < NCH; ++c) {
        if (c + 1 < NCH) {
            stage_load(c + 1, (c + 1) & 1);
            cp_commit();
            cp_wait<1>();
        } else {
            cp_wait<0>();
        }
        __syncthreads();

        const uint32_t sb = su + (c & 1) * STG_BYTES;
        #pragma unroll
        for (int ks = 0; ks < 4; ++ks) {
            // A fragments, both limbs, held in registers for reuse
            uint32_t a0[2][4], a1[2][4];
            #pragma unroll
            for (int mi = 0; mi < 2; ++mi) {
                int row = wm * 32 + mi * 16 + (lane & 15);
                uint32_t o = SWZ((uint32_t)(row * 128 + ks * 32 + ((lane >> 4) << 4)));
                asm volatile(
                    "ldmatrix.sync.aligned.m8n8.x4.shared.b16 {%0,%1,%2,%3}, [%4];"
                    : "=r"(a0[mi][0]), "=r"(a0[mi][1]), "=r"(a0[mi][2]), "=r"(a0[mi][3])
                    : "r"(sb + o));
                asm volatile(
                    "ldmatrix.sync.aligned.m8n8.x4.shared.b16 {%0,%1,%2,%3}, [%4];"
                    : "=r"(a1[mi][0]), "=r"(a1[mi][1]), "=r"(a1[mi][2]), "=r"(a1[mi][3])
                    : "r"(sb + OFF_A1 + o));
            }
            // per-ni: load B0,B1 frags once, issue 3 limb-products x 2 mi
            #pragma unroll
            for (int ni = 0; ni < 6; ++ni) {
                int n = wn * 48 + ni * 8 + (lane >> 2);
                uint32_t oj0 = SWZ((uint32_t)(n * 128 + ks * 32 + (lane & 3) * 4));
                uint32_t oj1 = SWZ((uint32_t)(n * 128 + ks * 32 + 16 + (lane & 3) * 4));
                uint32_t b00, b01, b10, b11;
                asm volatile("ld.shared.b32 %0, [%1];" : "=r"(b00) : "r"(sb + OFF_B0 + oj0));
                asm volatile("ld.shared.b32 %0, [%1];" : "=r"(b01) : "r"(sb + OFF_B0 + oj1));
                asm volatile("ld.shared.b32 %0, [%1];" : "=r"(b10) : "r"(sb + OFF_B1 + oj0));
                asm volatile("ld.shared.b32 %0, [%1];" : "=r"(b11) : "r"(sb + OFF_B1 + oj1));
                #pragma unroll
                for (int mi = 0; mi < 2; ++mi) {
                    asm volatile(
                        "mma.sync.aligned.m16n8k16.row.col.f32.f16.f16.f32 "
                        "{%0,%1,%2,%3}, {%4,%5,%6,%7}, {%8,%9}, {%0,%1,%2,%3};"
                        : "+f"(acc[mi][ni][0]), "+f"(acc[mi][ni][1]),
                          "+f"(acc[mi][ni][2]), "+f"(acc[mi][ni][3])
                        : "r"(a0[mi][0]), "r"(a0[mi][1]), "r"(a0[mi][2]), "r"(a0[mi][3]),
                          "r"(b00), "r"(b01));
                    asm volatile(
                        "mma.sync.aligned.m16n8k16.row.col.f32.f16.f16.f32 "
                        "{%0,%1,%2,%3}, {%4,%5,%6,%7}, {%8,%9}, {%0,%1,%2,%3};"
                        : "+f"(acc[mi][ni][0]), "+f"(acc[mi][ni][1]),
                          "+f"(acc[mi][ni][2]), "+f"(acc[mi][ni][3])
                        : "r"(a1[mi][0]), "r"(a1[mi][1]), "r"(a1[mi][2]), "r"(a1[mi][3]),
                          "r"(b00), "r"(b01));
                    asm volatile(
                        "mma.sync.aligned.m16n8k16.row.col.f32.f16.f16.f32 "
                        "{%0,%1,%2,%3}, {%4,%5,%6,%7}, {%8,%9}, {%0,%1,%2,%3};"
                        : "+f"(acc[mi][ni][0]), "+f"(acc[mi][ni][1]),
                          "+f"(acc[mi][ni][2]), "+f"(acc[mi][ni][3])
                        : "r"(a0[mi][0]), "r"(a0[mi][1]), "r"(a0[mi][2]), "r"(a0[mi][3]),
                          "r"(b10), "r"(b11));
                }
            }
        }
        __syncthreads();   // stage (c&1) free for load issued at iter c+1
    }

    // ---- epilogue: C -> SMEM roundtrip (co-locate r/z/n), then gate math ----
    float* sC = (float*)smem;   // [128][100], overlays stage 0 (mainloop done)
    #pragma unroll
    for (int mi = 0; mi < 2; ++mi)
        #pragma unroll
        for (int ni = 0; ni < 6; ++ni) {
            int row = wm * 32 + mi * 16 + (lane >> 2);
            int col = wn * 48 + ni * 8 + 2 * (lane & 3);
            sC[row * 100 + col]           = acc[mi][ni][0];
            sC[row * 100 + col + 1]       = acc[mi][ni][1];
            sC[(row + 8) * 100 + col]     = acc[mi][ni][2];
            sC[(row + 8) * 100 + col + 1] = acc[mi][ni][3];
        }
    __syncthreads();

    {
        const int m_l = tid >> 1, jh = tid & 1;
        const int mg = m0 + m_l;
        const int token = (HH == H1) ? toks[mg * S_ + t] : g_tok[mg];
        const float* pr = &proj[token * (3 * HH)];
        __half* ph0 = (__half*)hn0;
        __half* ph1 = (__half*)hn1;
        #pragma unroll
        for (int q = 0; q < 16; ++q) {
            int jl = jh * 16 + q;
            int jj = j0 + jl;
            float h_r = sC[m_l * 100 + jl]      + bhh[jj];
            float h_z = sC[m_l * 100 + 32 + jl] + bhh[HH + jj];
            float h_n = sC[m_l * 100 + 64 + jl] + bhh[2 * HH + jj];
            float r = sigmoid_(pr[jj] + h_r);
            float z = sigmoid_(pr[HH + jj] + h_z);
            float n = tanh_(pr[2 * HH + jj] + r * h_n);
            float ho = hold[mg * HH + jj];
            float hv = (1.f - z) * n + z * ho;
            hnew[mg * HH + jj] = hv;
            __half a0h, a1h;
            split2h(hv, a0h, a1h);
            ph0[mg * HH + jj] = a0h;
            ph1[mg * HH + jj] = a1h;
        }
    }
}

// ---------------- logits: split-K partial GEMM + reduce/argmax ----------------
__global__ __launch_bounds__(256)
void logits_partial_kernel(const float* __restrict__ Wfc, int pp)
{
    const float* hh = g_hh[pp ^ 1];
    const int b0 = blockIdx.x * 32;
    const int ks = blockIdx.y * 256;
    const int tid = threadIdx.x;
    const int tx = tid & 31, ty = tid >> 5;

    __shared__ float sA[32][32];
    __shared__ float sB[32][128];

    float acc[4][4];
    #pragma unroll
    for (int i = 0; i < 4; i++)
        #pragma unroll
        for (int j = 0; j < 4; j++) acc[i][j] = 0.f;

    for (int k0 = ks; k0 < ks + 256; k0 += 32) {
        {
            int r = tid >> 3, k4 = (tid & 7) * 4;
            float4 v = *(const float4*)&hh[(b0 + r) * H2 + k0 + k4];
            sA[k4 + 0][r] = v.x; sA[k4 + 1][r] = v.y;
            sA[k4 + 2][r] = v.z; sA[k4 + 3][r] = v.w;
        }
        #pragma unroll
        for (int it = 0; it < 4; ++it) {
            int idx = tid + it * 256;
            int r = idx >> 3, k4 = (idx & 7) * 4;
            float4 v = *(const float4*)&Wfc[r * H2 + k0 + k4];
            sB[k4 + 0][r] = v.x; sB[k4 + 1][r] = v.y;
            sB[k4 + 2][r] = v.z; sB[k4 + 3][r] = v.w;
        }
        __syncthreads();
        #pragma unroll
        for (int kk = 0; kk < 32; ++kk) {
            float4 a4 = *(const float4*)&sA[kk][ty * 4];
            float4 b4 = *(const float4*)&sB[kk][tx * 4];
            float a[4] = {a4.x, a4.y, a4.z, a4.w};
            float wv[4] = {b4.x, b4.y, b4.z, b4.w};
            #pragma unroll
            for (int i = 0; i < 4; i++)
                #pragma unroll
                for (int j = 0; j < 4; j++)
                    acc[i][j] = fmaf(a[i], wv[j], acc[i][j]);
        }
        __syncthreads();
    }

    #pragma unroll
    for (int i = 0; i < 4; i++)
        #pragma unroll
        for (int j = 0; j < 4; j++)
            g_part[blockIdx.y][(b0 + ty * 4 + i) * V_ + tx * 4 + j] = acc[i][j];
}

__global__ void logits_reduce_kernel(const float* __restrict__ bfc,
                                     float* __restrict__ out, int t)
{
    const int b = blockIdx.x;
    const int v = threadIdx.x;
    float s = bfc[v];
    #pragma unroll
    for (int p = 0; p < 8; p++) s += g_part[p][b * V_ + v];
    out[(b * (T_ - 1) + t) * V_ + v] = s;

    __shared__ float sv[V_];
    __shared__ int   si[V_];
    sv[v] = s; si[v] = v;
    __syncthreads();
    for (int off = 64; off > 0; off >>= 1) {
        if (v < off) {
            float o = sv[v + off]; int oi = si[v + off];
            if (o > sv[v] || (o == sv[v] && oi < si[v])) { sv[v] = o; si[v] = oi; }
        }
        __syncthreads();
    }
    if (v == 0) g_tok[b] = si[0];
}

// ---------------- init kernels ----------------
__global__ void init_enc_kernel()
{
    int i = blockIdx.x * blockDim.x + threadIdx.x;
    if (i < B_ * H1) { g_hf[0][i] = 0.f; g_hb[0][i] = 0.f; }
    if (i < B_ * H1 / 8) {
        uint4 z = make_uint4(0, 0, 0, 0);
        g_hf_l0[0][i] = z; g_hf_l1[0][i] = z;
        g_hb_l0[0][i] = z; g_hb_l1[0][i] = z;
    }
}

__global__ void init_dec_kernel(const int* __restrict__ tgt)
{
    int i = blockIdx.x * blockDim.x + threadIdx.x;
    if (i < B_ * H2) {
        int b = i >> 11, j = i & (H2 - 1);
        float v = (j < H1) ? g_hf[0][b * H1 + j] : g_hb[0][b * H1 + (j - H1)];
        g_hh[0][i] = v;
        __half a0, a1;
        split2h(v, a0, a1);
        ((__half*)g_hh_l0[0])[i] = a0;
        ((__half*)g_hh_l1[0])[i] = a1;
    }
    if (i < B_) g_tok[i] = tgt[i * T_];
}

// ---------------- launch ----------------
extern "C" void kernel_launch(void* const* d_in, const int* in_sizes, int n_in,
                              void* d_out, int out_size)
{
    const int*   src     = (const int*)d_in[0];
    const int*   tgt     = (const int*)d_in[1];
    const float* enc_emb = (const float*)d_in[2];
    const float* dec_emb = (const float*)d_in[3];
    const float* W_ih_f  = (const float*)d_in[4];
    const float* W_hh_f  = (const float*)d_in[5];
    const float* b_ih_f  = (const float*)d_in[6];
    const float* b_hh_f  = (const float*)d_in[7];
    const float* W_ih_b  = (const float*)d_in[8];
    const float* W_hh_b  = (const float*)d_in[9];
    const float* b_ih_b  = (const float*)d_in[10];
    const float* b_hh_b  = (const float*)d_in[11];
    const float* W_ih_d  = (const float*)d_in[12];
    const float* W_hh_d  = (const float*)d_in[13];
    const float* b_ih_d  = (const float*)d_in[14];
    const float* b_hh_d  = (const float*)d_in[15];
    const float* W_fc    = (const float*)d_in[16];
    const float* b_fc    = (const float*)d_in[17];
    float* out = (float*)d_out;

    const int SMEM = 2 * STG_BYTES;   // 112KB: 2 stages; epilogue C (51.2KB) overlays
    cudaFuncSetAttribute(gru_step_mma<H1>,
        cudaFuncAttributeMaxDynamicSharedMemorySize, SMEM);
    cudaFuncSetAttribute(gru_step_mma<H2>,
        cudaFuncAttributeMaxDynamicSharedMemorySize, SMEM);

    // one-time per replay: proj tables + weight limb splits
    proj_kernel<<<dim3(3 * H1 / 64, 2), 256>>>(enc_emb, W_ih_f, b_ih_f, 0, 3 * H1);
    proj_kernel<<<dim3(3 * H1 / 64, 2), 256>>>(enc_emb, W_ih_b, b_ih_b, 1, 3 * H1);
    proj_kernel<<<dim3(3 * H2 / 64, 2), 256>>>(dec_emb, W_ih_d, b_ih_d, 2, 3 * H2);
    split_w_kernel<<<(3 * H1 * H1 + 255) / 256, 256>>>(W_hh_f, 0, 3 * H1 * H1);
    split_w_kernel<<<(3 * H1 * H1 + 255) / 256, 256>>>(W_hh_b, 1, 3 * H1 * H1);
    split_w_kernel<<<(3 * H2 * H2 + 255) / 256, 256>>>(W_hh_d, 2, 3 * H2 * H2);

    init_enc_kernel<<<(B_ * H1 + 511) / 512, 512>>>();

    for (int s = 0; s < S_; s++)
        gru_step_mma<H1><<<dim3(H1 / 32, B_ / 128, 2), 256, SMEM>>>(
            src, b_hh_f, b_hh_b, s & 1, s);
    // s=63: pp=1 -> writes buffer 0; final encoder state in buffer 0

    init_dec_kernel<<<(B_ * H2 + 255) / 256, 256>>>(tgt);

    for (int t = 0; t < T_ - 1; t++) {
        gru_step_mma<H2><<<dim3(H2 / 32, B_ / 128, 1), 256, SMEM>>>(
            (const int*)nullptr, b_hh_d, b_hh_d, t & 1, 0);
        logits_partial_kernel<<<dim3(B_ / 32, 8), 256>>>(W_fc, t & 1);
        logits_reduce_kernel<<<B_, V_>>>(b_fc, out, t);
    }
}

// round 11
// speedup vs baseline: 2.7715x; 1.0489x over previous
#include <cuda_runtime.h>
#include <cuda_fp16.h>
#include <cstdint>

// Seq2Seq GRU with HMMA (mma.sync m16n8k16 fp16->fp32), fp32-faithful via
// 2-limb fp16 decomposition x = h0 + h1; 3 limb products (A0B0+A1B0+A0B1)
// issued from registers. cp.async double-buffered staging (2 x 56KB).
// R11: B fragments via ldmatrix.x4 (24 lds.32 -> 6 ldsm per warp-slice);
//      prep fused into 2 kernels (proj_all, split_all) for ncu visibility.

static const int B_ = 512;
static const int S_ = 64;
static const int T_ = 32;
static const int E_ = 512;
static const int H1 = 1024;
static const int H2 = 2048;
static const int V_ = 128;

// stage layout (bytes): A0 @ 0 (16K), A1 @ 16K, B0 @ 32K (12K), B1 @ 44K; 56K total
static const int STG_BYTES = 57344;
static const int OFF_A1 = 16384;
static const int OFF_B0 = 32768;
static const int OFF_B1 = 45056;

// ---------------- device scratch ----------------
__device__ float g_proj_f[V_ * 3 * H1];
__device__ float g_proj_b[V_ * 3 * H1];
__device__ float g_proj_d[V_ * 3 * H2];
__device__ float g_hf[2][B_ * H1];
__device__ float g_hb[2][B_ * H1];
__device__ float g_hh[2][B_ * H2];
__device__ uint4 g_hf_l0[2][B_ * H1 / 8];
__device__ uint4 g_hf_l1[2][B_ * H1 / 8];
__device__ uint4 g_hb_l0[2][B_ * H1 / 8];
__device__ uint4 g_hb_l1[2][B_ * H1 / 8];
__device__ uint4 g_hh_l0[2][B_ * H2 / 8];
__device__ uint4 g_hh_l1[2][B_ * H2 / 8];
__device__ uint4 g_Wf_l0[3 * H1 * H1 / 8];
__device__ uint4 g_Wf_l1[3 * H1 * H1 / 8];
__device__ uint4 g_Wb_l0[3 * H1 * H1 / 8];
__device__ uint4 g_Wb_l1[3 * H1 * H1 / 8];
__device__ uint4 g_Wd_l0[3 * H2 * H2 / 8];
__device__ uint4 g_Wd_l1[3 * H2 * H2 / 8];
__device__ float g_part[8][B_ * V_];
__device__ int   g_tok[B_];

__device__ __forceinline__ float sigmoid_(float x) { return 1.f / (1.f + __expf(-x)); }
__device__ __forceinline__ float tanh_(float x) {
    float e = __expf(2.f * x);
    return 1.f - 2.f / (e + 1.f);
}

#define SWZ(o) ((o) ^ (((o) >> 3) & 0x70))

__device__ __forceinline__ uint32_t smem_u32(const void* p) {
    uint32_t a;
    asm("{ .reg .u64 t; cvta.to.shared.u64 t, %1; cvt.u32.u64 %0, t; }" : "=r"(a) : "l"(p));
    return a;
}
__device__ __forceinline__ void split2h(float x, __half& a0, __half& a1) {
    a0 = __float2half_rn(x);
    a1 = __float2half_rn(x - __half2float(a0));
}
__device__ __forceinline__ void cp16(uint32_t dst, const void* src) {
    asm volatile("cp.async.cg.shared.global [%0], [%1], 16;" :: "r"(dst), "l"(src));
}
__device__ __forceinline__ void cp_commit() {
    asm volatile("cp.async.commit_group;" ::: "memory");
}
template<int N>
__device__ __forceinline__ void cp_wait() {
    asm volatile("cp.async.wait_group %0;" :: "n"(N) : "memory");
}

// ---------------- fused prep: limb-split all weights + zero encoder h ----------------
static const int NF = 3 * H1 * H1;       // f weights
static const int ND = 3 * H2 * H2;       // d weights
__global__ void split_all_kernel(const float* __restrict__ Wf,
                                 const float* __restrict__ Wb,
                                 const float* __restrict__ Wd)
{
    long long i = (long long)blockIdx.x * blockDim.x + threadIdx.x;
    // zero encoder h (fp32 + limbs)
    if (i < B_ * H1) { g_hf[0][i] = 0.f; g_hb[0][i] = 0.f; }
    if (i < B_ * H1 / 8) {
        uint4 z = make_uint4(0, 0, 0, 0);
        g_hf_l0[0][i] = z; g_hf_l1[0][i] = z;
        g_hb_l0[0][i] = z; g_hb_l1[0][i] = z;
    }
    const float* src; __half *o0, *o1; long long k;
    if (i < NF)               { src = Wf; k = i;            o0 = (__half*)g_Wf_l0; o1 = (__half*)g_Wf_l1; }
    else if (i < 2LL * NF)    { src = Wb; k = i - NF;       o0 = (__half*)g_Wb_l0; o1 = (__half*)g_Wb_l1; }
    else if (i < 2LL * NF + ND) { src = Wd; k = i - 2LL * NF; o0 = (__half*)g_Wd_l0; o1 = (__half*)g_Wd_l1; }
    else return;
    __half a0, a1;
    split2h(src[k], a0, a1);
    o0[k] = a0; o1[k] = a1;
}

// ---------------- fused projection tables: out[128][N] = Emb @ W^T + b ----------------
__global__ __launch_bounds__(256)
void proj_all_kernel(const float* __restrict__ enc_emb, const float* __restrict__ dec_emb,
                     const float* __restrict__ Wf, const float* __restrict__ Wb,
                     const float* __restrict__ Wd,
                     const float* __restrict__ bf, const float* __restrict__ bb,
                     const float* __restrict__ bd)
{
    const int which = blockIdx.z;
    const int N = (which == 2) ? 3 * H2 : 3 * H1;
    if (blockIdx.x * 64 >= N) return;
    const float* Emb = (which == 2) ? dec_emb : enc_emb;
    const float* W   = (which == 0) ? Wf : (which == 1) ? Wb : Wd;
    const float* b   = (which == 0) ? bf : (which == 1) ? bb : bd;
    float* out = (which == 0) ? g_proj_f : (which == 1) ? g_proj_b : g_proj_d;

    const int n0 = blockIdx.x * 64, m0 = blockIdx.y * 64;
    const int tid = threadIdx.x;
    const int tx = tid & 15, ty = tid >> 4;

    __shared__ float sA[32][64];
    __shared__ float sB[32][64];

    float acc[4][4];
    #pragma unroll
    for (int i = 0; i < 4; i++)
        #pragma unroll
        for (int j = 0; j < 4; j++) acc[i][j] = 0.f;

    for (int k0 = 0; k0 < E_; k0 += 32) {
        #pragma unroll
        for (int it = 0; it < 2; ++it) {
            int idx = tid + it * 256;
            int r = idx >> 3, k4 = (idx & 7) * 4;
            float4 v = *(const float4*)&Emb[(m0 + r) * E_ + k0 + k4];
            sA[k4 + 0][r] = v.x; sA[k4 + 1][r] = v.y;
            sA[k4 + 2][r] = v.z; sA[k4 + 3][r] = v.w;
        }
        #pragma unroll
        for (int it = 0; it < 2; ++it) {
            int idx = tid + it * 256;
            int r = idx >> 3, k4 = (idx & 7) * 4;
            float4 v = *(const float4*)&W[(n0 + r) * E_ + k0 + k4];
            sB[k4 + 0][r] = v.x; sB[k4 + 1][r] = v.y;
            sB[k4 + 2][r] = v.z; sB[k4 + 3][r] = v.w;
        }
        __syncthreads();
        #pragma unroll
        for (int kk = 0; kk < 32; ++kk) {
            float4 a4 = *(const float4*)&sA[kk][ty * 4];
            float4 b4 = *(const float4*)&sB[kk][tx * 4];
            float a[4] = {a4.x, a4.y, a4.z, a4.w};
            float w[4] = {b4.x, b4.y, b4.z, b4.w};
            #pragma unroll
            for (int i = 0; i < 4; i++)
                #pragma unroll
                for (int j = 0; j < 4; j++)
                    acc[i][j] = fmaf(a[i], w[j], acc[i][j]);
        }
        __syncthreads();
    }

    #pragma unroll
    for (int i = 0; i < 4; i++) {
        int m = m0 + ty * 4 + i;
        #pragma unroll
        for (int j = 0; j < 4; j++) {
            int n = n0 + tx * 4 + j;
            out[m * N + n] = acc[i][j] + b[n];
        }
    }
}

// ---------------- HMMA GRU step (ldmatrix B frags + cp.async pipeline) ----------------
// CTA: 128 batch (blockIdx.y) x 32 j (blockIdx.x) x 3 gates -> N=96.
// 2 stages x 56KB; epilogue reuses SMEM as fp32 C [128][100].
template<int HH>
__global__ __launch_bounds__(256, 2)
void gru_step_mma(const int* __restrict__ toks, const float* __restrict__ bhh_a,
                  const float* __restrict__ bhh_b, int pp, int s)
{
    extern __shared__ char smem[];
    const uint32_t su = smem_u32(smem);
    const int tid = threadIdx.x;

    const uint4 *w0, *w1, *h0p, *h1p;
    uint4 *hn0, *hn1;
    const float *hold, *bhh, *proj;
    float* hnew;
    int t = 0;
    if (HH == H1) {
        const int dir = blockIdx.z;
        if (dir == 0) {
            w0 = g_Wf_l0; w1 = g_Wf_l1;
            h0p = g_hf_l0[pp]; h1p = g_hf_l1[pp];
            hn0 = g_hf_l0[pp ^ 1]; hn1 = g_hf_l1[pp ^ 1];
            hold = g_hf[pp]; hnew = g_hf[pp ^ 1];
            bhh = bhh_a; proj = g_proj_f; t = s;
        } else {
            w0 = g_Wb_l0; w1 = g_Wb_l1;
            h0p = g_hb_l0[pp]; h1p = g_hb_l1[pp];
            hn0 = g_hb_l0[pp ^ 1]; hn1 = g_hb_l1[pp ^ 1];
            hold = g_hb[pp]; hnew = g_hb[pp ^ 1];
            bhh = bhh_b; proj = g_proj_b; t = S_ - 1 - s;
        }
    } else {
        w0 = g_Wd_l0; w1 = g_Wd_l1;
        h0p = g_hh_l0[pp]; h1p = g_hh_l1[pp];
        hn0 = g_hh_l0[pp ^ 1]; hn1 = g_hh_l1[pp ^ 1];
        hold = g_hh[pp]; hnew = g_hh[pp ^ 1];
        bhh = bhh_a; proj = g_proj_d;
    }

    const int m0 = blockIdx.y * 128;
    const int j0 = blockIdx.x * 32;

    const int w = tid >> 5, lane = tid & 31;
    const int wm = w >> 1, wn = w & 1;       // 4 x 2 warp grid: M=32, N=48 per warp

    float acc[2][6][4];
    #pragma unroll
    for (int mi = 0; mi < 2; ++mi)
        #pragma unroll
        for (int ni = 0; ni < 6; ++ni)
            #pragma unroll
            for (int q = 0; q < 4; ++q) acc[mi][ni][q] = 0.f;

    const int NCH = HH / 64;

    auto stage_load = [&](int c, int st) {
        const int k0 = c * 64;
        const uint32_t sb = su + st * STG_BYTES;
        #pragma unroll
        for (int it = 0; it < 4; ++it) {
            int idx = tid + it * 256;
            int r = idx >> 3, kb = idx & 7;
            int gi = ((m0 + r) * HH + k0) / 8 + kb;
            uint32_t o = SWZ((uint32_t)(r * 128 + kb * 16));
            cp16(sb + o, &h0p[gi]);
            cp16(sb + OFF_A1 + o, &h1p[gi]);
        }
        #pragma unroll
        for (int it = 0; it < 3; ++it) {
            int idx = tid + it * 256;
            int rsm = idx >> 3, kb = idx & 7;
            int g = rsm >> 5, jl = rsm & 31;
            int gi = ((g * HH + j0 + jl) * HH + k0) / 8 + kb;
            uint32_t o = SWZ((uint32_t)(rsm * 128 + kb * 16));
            cp16(sb + OFF_B0 + o, &w0[gi]);
            cp16(sb + OFF_B1 + o, &w1[gi]);
        }
    };

    stage_load(0, 0);
    cp_commit();

    // per-lane constants for B ldmatrix.x4: quad 0,1 -> limb0 (k lo/hi 16B), quad 2,3 -> limb1
    const int bquad = lane >> 3;
    const uint32_t blimb_off = (bquad >= 2) ? (uint32_t)OFF_B1 : (uint32_t)OFF_B0;
    const uint32_t bk_off = (uint32_t)(bquad & 1) * 16;
    const int bn_lane = lane & 7;

    for (int c = 0; c < NCH; ++c) {
        if (c + 1 < NCH) {
            stage_load(c + 1, (c + 1) & 1);
            cp_commit();
            cp_wait<1>();
        } else {
            cp_wait<0>();
        }
        __syncthreads();

        const uint32_t sb = su + (c & 1) * STG_BYTES;
        #pragma unroll
        for (int ks = 0; ks < 4; ++ks) {
            uint32_t a0[2][4], a1[2][4];
            #pragma unroll
            for (int mi = 0; mi < 2; ++mi) {
                int row = wm * 32 + mi * 16 + (lane & 15);
                uint32_t o = SWZ((uint32_t)(row * 128 + ks * 32 + ((lane >> 4) << 4)));
                asm volatile(
                    "ldmatrix.sync.aligned.m8n8.x4.shared.b16 {%0,%1,%2,%3}, [%4];"
                    : "=r"(a0[mi][0]), "=r"(a0[mi][1]), "=r"(a0[mi][2]), "=r"(a0[mi][3])
                    : "r"(sb + o));
                asm volatile(
                    "ldmatrix.sync.aligned.m8n8.x4.shared.b16 {%0,%1,%2,%3}, [%4];"
                    : "=r"(a1[mi][0]), "=r"(a1[mi][1]), "=r"(a1[mi][2]), "=r"(a1[mi][3])
                    : "r"(sb + OFF_A1 + o));
            }
            #pragma unroll
            for (int ni = 0; ni < 6; ++ni) {
                // one ldmatrix.x4 (no trans): {b00,b01,b10,b11} for this n-slice
                int nrow = wn * 48 + ni * 8 + bn_lane;
                uint32_t baddr = sb + blimb_off
                               + SWZ((uint32_t)(nrow * 128 + ks * 32 + bk_off));
                uint32_t b00, b01, b10, b11;
                asm volatile(
                    "ldmatrix.sync.aligned.m8n8.x4.shared.b16 {%0,%1,%2,%3}, [%4];"
                    : "=r"(b00), "=r"(b01), "=r"(b10), "=r"(b11)
                    : "r"(baddr));
                #pragma unroll
                for (int mi = 0; mi < 2; ++mi) {
                    asm volatile(
                        "mma.sync.aligned.m16n8k16.row.col.f32.f16.f16.f32 "
                        "{%0,%1,%2,%3}, {%4,%5,%6,%7}, {%8,%9}, {%0,%1,%2,%3};"
                        : "+f"(acc[mi][ni][0]), "+f"(acc[mi][ni][1]),
                          "+f"(acc[mi][ni][2]), "+f"(acc[mi][ni][3])
                        : "r"(a0[mi][0]), "r"(a0[mi][1]), "r"(a0[mi][2]), "r"(a0[mi][3]),
                          "r"(b00), "r"(b01));
                    asm volatile(
                        "mma.sync.aligned.m16n8k16.row.col.f32.f16.f16.f32 "
                        "{%0,%1,%2,%3}, {%4,%5,%6,%7}, {%8,%9}, {%0,%1,%2,%3};"
                        : "+f"(acc[mi][ni][0]), "+f"(acc[mi][ni][1]),
                          "+f"(acc[mi][ni][2]), "+f"(acc[mi][ni][3])
                        : "r"(a1[mi][0]), "r"(a1[mi][1]), "r"(a1[mi][2]), "r"(a1[mi][3]),
                          "r"(b00), "r"(b01));
                    asm volatile(
                        "mma.sync.aligned.m16n8k16.row.col.f32.f16.f16.f32 "
                        "{%0,%1,%2,%3}, {%4,%5,%6,%7}, {%8,%9}, {%0,%1,%2,%3};"
                        : "+f"(acc[mi][ni][0]), "+f"(acc[mi][ni][1]),
                          "+f"(acc[mi][ni][2]), "+f"(acc[mi][ni][3])
                        : "r"(a0[mi][0]), "r"(a0[mi][1]), "r"(a0[mi][2]), "r"(a0[mi][3]),
                          "r"(b10), "r"(b11));
                }
            }
        }
        __syncthreads();
    }

    // ---- epilogue: C -> SMEM roundtrip (co-locate r/z/n), then gate math ----
    float* sC = (float*)smem;   // [128][100]
    #pragma unroll
    for (int mi = 0; mi < 2; ++mi)
        #pragma unroll
        for (int ni = 0; ni < 6; ++ni) {
            int row = wm * 32 + mi * 16 + (lane >> 2);
            int col = wn * 48 + ni * 8 + 2 * (lane & 3);
            sC[row * 100 + col]           = acc[mi][ni][0];
            sC[row * 100 + col + 1]       = acc[mi][ni][1];
            sC[(row + 8) * 100 + col]     = acc[mi][ni][2];
            sC[(row + 8) * 100 + col + 1] = acc[mi][ni][3];
        }
    __syncthreads();

    {
        const int m_l = tid >> 1, jh = tid & 1;
        const int mg = m0 + m_l;
        const int token = (HH == H1) ? toks[mg * S_ + t] : g_tok[mg];
        const float* pr = &proj[token * (3 * HH)];
        __half* ph0 = (__half*)hn0;
        __half* ph1 = (__half*)hn1;
        #pragma unroll
        for (int q = 0; q < 16; ++q) {
            int jl = jh * 16 + q;
            int jj = j0 + jl;
            float h_r = sC[m_l * 100 + jl]      + bhh[jj];
            float h_z = sC[m_l * 100 + 32 + jl] + bhh[HH + jj];
            float h_n = sC[m_l * 100 + 64 + jl] + bhh[2 * HH + jj];
            float r = sigmoid_(pr[jj] + h_r);
            float z = sigmoid_(pr[HH + jj] + h_z);
            float n = tanh_(pr[2 * HH + jj] + r * h_n);
            float ho = hold[mg * HH + jj];
            float hv = (1.f - z) * n + z * ho;
            hnew[mg * HH + jj] = hv;
            __half a0h, a1h;
            split2h(hv, a0h, a1h);
            ph0[mg * HH + jj] = a0h;
            ph1[mg * HH + jj] = a1h;
        }
    }
}

// ---------------- logits: split-K partial GEMM + reduce/argmax ----------------
__global__ __launch_bounds__(256)
void logits_partial_kernel(const float* __restrict__ Wfc, int pp)
{
    const float* hh = g_hh[pp ^ 1];
    const int b0 = blockIdx.x * 32;
    const int ks = blockIdx.y * 256;
    const int tid = threadIdx.x;
    const int tx = tid & 31, ty = tid >> 5;

    __shared__ float sA[32][32];
    __shared__ float sB[32][128];

    float acc[4][4];
    #pragma unroll
    for (int i = 0; i < 4; i++)
        #pragma unroll
        for (int j = 0; j < 4; j++) acc[i][j] = 0.f;

    for (int k0 = ks; k0 < ks + 256; k0 += 32) {
        {
            int r = tid >> 3, k4 = (tid & 7) * 4;
            float4 v = *(const float4*)&hh[(b0 + r) * H2 + k0 + k4];
            sA[k4 + 0][r] = v.x; sA[k4 + 1][r] = v.y;
            sA[k4 + 2][r] = v.z; sA[k4 + 3][r] = v.w;
        }
        #pragma unroll
        for (int it = 0; it < 4; ++it) {
            int idx = tid + it * 256;
            int r = idx >> 3, k4 = (idx & 7) * 4;
            float4 v = *(const float4*)&Wfc[r * H2 + k0 + k4];
            sB[k4 + 0][r] = v.x; sB[k4 + 1][r] = v.y;
            sB[k4 + 2][r] = v.z; sB[k4 + 3][r] = v.w;
        }
        __syncthreads();
        #pragma unroll
        for (int kk = 0; kk < 32; ++kk) {
            float4 a4 = *(const float4*)&sA[kk][ty * 4];
            float4 b4 = *(const float4*)&sB[kk][tx * 4];
            float a[4] = {a4.x, a4.y, a4.z, a4.w};
            float wv[4] = {b4.x, b4.y, b4.z, b4.w};
            #pragma unroll
            for (int i = 0; i < 4; i++)
                #pragma unroll
                for (int j = 0; j < 4; j++)
                    acc[i][j] = fmaf(a[i], wv[j], acc[i][j]);
        }
        __syncthreads();
    }

    #pragma unroll
    for (int i = 0; i < 4; i++)
        #pragma unroll
        for (int j = 0; j < 4; j++)
            g_part[blockIdx.y][(b0 + ty * 4 + i) * V_ + tx * 4 + j] = acc[i][j];
}

__global__ void logits_reduce_kernel(const float* __restrict__ bfc,
                                     float* __restrict__ out, int t)
{
    const int b = blockIdx.x;
    const int v = threadIdx.x;
    float s = bfc[v];
    #pragma unroll
    for (int p = 0; p < 8; p++) s += g_part[p][b * V_ + v];
    out[(b * (T_ - 1) + t) * V_ + v] = s;

    __shared__ float sv[V_];
    __shared__ int   si[V_];
    sv[v] = s; si[v] = v;
    __syncthreads();
    for (int off = 64; off > 0; off >>= 1) {
        if (v < off) {
            float o = sv[v + off]; int oi = si[v + off];
            if (o > sv[v] || (o == sv[v] && oi < si[v])) { sv[v] = o; si[v] = oi; }
        }
        __syncthreads();
    }
    if (v == 0) g_tok[b] = si[0];
}

// ---------------- init decoder ----------------
__global__ void init_dec_kernel(const int* __restrict__ tgt)
{
    int i = blockIdx.x * blockDim.x + threadIdx.x;
    if (i < B_ * H2) {
        int b = i >> 11, j = i & (H2 - 1);
        float v = (j < H1) ? g_hf[0][b * H1 + j] : g_hb[0][b * H1 + (j - H1)];
        g_hh[0][i] = v;
        __half a0, a1;
        split2h(v, a0, a1);
        ((__half*)g_hh_l0[0])[i] = a0;
        ((__half*)g_hh_l1[0])[i] = a1;
    }
    if (i < B_) g_tok[i] = tgt[i * T_];
}

// ---------------- launch ----------------
extern "C" void kernel_launch(void* const* d_in, const int* in_sizes, int n_in,
                              void* d_out, int out_size)
{
    const int*   src     = (const int*)d_in[0];
    const int*   tgt     = (const int*)d_in[1];
    const float* enc_emb = (const float*)d_in[2];
    const float* dec_emb = (const float*)d_in[3];
    const float* W_ih_f  = (const float*)d_in[4];
    const float* W_hh_f  = (const float*)d_in[5];
    const float* b_ih_f  = (const float*)d_in[6];
    const float* b_hh_f  = (const float*)d_in[7];
    const float* W_ih_b  = (const float*)d_in[8];
    const float* W_hh_b  = (const float*)d_in[9];
    const float* b_ih_b  = (const float*)d_in[10];
    const float* b_hh_b  = (const float*)d_in[11];
    const float* W_ih_d  = (const float*)d_in[12];
    const float* W_hh_d  = (const float*)d_in[13];
    const float* b_ih_d  = (const float*)d_in[14];
    const float* b_hh_d  = (const float*)d_in[15];
    const float* W_fc    = (const float*)d_in[16];
    const float* b_fc    = (const float*)d_in[17];
    float* out = (float*)d_out;

    const int SMEM = 2 * STG_BYTES;   // 112KB
    cudaFuncSetAttribute(gru_step_mma<H1>,
        cudaFuncAttributeMaxDynamicSharedMemorySize, SMEM);
    cudaFuncSetAttribute(gru_step_mma<H2>,
        cudaFuncAttributeMaxDynamicSharedMemorySize, SMEM);

    // prep (2 launches): proj tables, then weight limb-split + encoder h zero
    proj_all_kernel<<<dim3(3 * H2 / 64, 2, 3), 256>>>(
        enc_emb, dec_emb, W_ih_f, W_ih_b, W_ih_d, b_ih_f, b_ih_b, b_ih_d);
    {
        long long total = 2LL * NF + ND;
        split_all_kernel<<<(unsigned)((total + 255) / 256), 256>>>(W_hh_f, W_hh_b, W_hh_d);
    }

    for (int s = 0; s < S_; s++)
        gru_step_mma<H1><<<dim3(H1 / 32, B_ / 128, 2), 256, SMEM>>>(
            src, b_hh_f, b_hh_b, s & 1, s);
    // s=63: pp=1 -> writes buffer 0; final encoder state in buffer 0

    init_dec_kernel<<<(B_ * H2 + 255) / 256, 256>>>(tgt);

    for (int t = 0; t < T_ - 1; t++) {
        gru_step_mma<H2><<<dim3(H2 / 32, B_ / 128, 1), 256, SMEM>>>(
            (const int*)nullptr, b_hh_d, b_hh_d, t & 1, 0);
        logits_partial_kernel<<<dim3(B_ / 32, 8), 256>>>(W_fc, t & 1);
        logits_reduce_kernel<<<B_, V_>>>(b_fc, out, t);
    }
}